// round 4
// baseline (speedup 1.0000x reference)
#include <cuda_runtime.h>
#include <math.h>

#define R_ 3
#define T_ 3
#define N_ 50000
#define OPS_ 24
#define E_ 400000
#define B_ 32
#define MAXDEG_ 8
#define QD_ 128
#define ED_ 128
#define H_ 128

// ---------------- scratch (device globals; no allocations allowed) ----------------
__device__ float g_xgI[2 * 25 * 512];        // xg interleaved [dir][d][j*4+g]
__device__ float g_WhhI[2 * 128 * 512];      // Whh interleaved [dir][k][j*4+g]
__device__ float g_eh[N_ * 256];             // entity BiLSTM final hidden (N, 2H)
__device__ float g_attn[N_ * OPS_];          // entity attention (N, 24)
__device__ float g_w[E_];                    // per-edge weight
__device__ float g_qys[R_ * 2 * T_ * B_ * H_];
__device__ float g_qaT[R_ * T_ * (OPS_ + 1) * B_];   // [rt][op][b]
__device__ float g_mem[N_ * B_];             // memory, layout (N, B)
__device__ float g_added[N_ * B_];
__device__ float g_gsum[B_];

__device__ __forceinline__ float sigm(float x) { return 1.f / (1.f + expf(-x)); }

// ---------------- precompute: xg[dir][d][j*4+g] = emb[d]@Wih^T + bih + bhh -------
__global__ void k_xg(const float* __restrict__ ent_emb, const float* __restrict__ e_Wih,
                     const float* __restrict__ e_bih, const float* __restrict__ e_bhh) {
    int d = blockIdx.x, dir = blockIdx.y, tid = threadIdx.x;  // 512 threads
    int j = tid >> 2, g = tid & 3;
    int row = g * 128 + j;
    const float* w = e_Wih + (dir * 512 + row) * 128;
    const float* x = ent_emb + d * 128;
    float s = e_bih[dir * 512 + row] + e_bhh[dir * 512 + row];
    for (int k = 0; k < 128; k++) s += x[k] * w[k];
    g_xgI[(dir * 25 + d) * 512 + tid] = s;
}

// ---------------- precompute: WhhI[dir][k][j*4+g] = Whh[dir][g*128+j][k] ---------
__global__ void k_whhT(const float* __restrict__ e_Whh) {
    int k = blockIdx.x, dir = blockIdx.y, tid = threadIdx.x;  // 512 threads
    int j = tid >> 2, g = tid & 3;
    g_WhhI[(dir * 128 + k) * 512 + tid] = e_Whh[(dir * 512 + g * 128 + j) * 128 + k];
}

// ---------------- entity BiLSTM: the heavy kernel --------------------------------
#define EK_THREADS 512
#define TILE_M 32
#define SH_PITCH 36

__global__ void __launch_bounds__(EK_THREADS) k_entity(const int* __restrict__ degrees) {
    extern __shared__ float smem[];
    float* sB = smem;                              // 2 * 16 * 512 floats (double buffer)
    float* sh = smem + 2 * 16 * 512;               // hT: [128][36] padded
    int* sdeg = (int*)(sh + 128 * SH_PITCH);       // [32][8]

    int dir = blockIdx.y;
    int n0 = blockIdx.x * TILE_M;
    int tid = threadIdx.x;

    if (tid < TILE_M * MAXDEG_) {
        int m = tid >> 3, t = tid & 7;
        int n = n0 + m;
        int d = (n < N_) ? degrees[n * MAXDEG_ + (dir ? (MAXDEG_ - 1 - t) : t)] : OPS_;
        sdeg[m * MAXDEG_ + t] = d;
    }
    for (int i = tid; i < 128 * SH_PITCH; i += EK_THREADS) sh[i] = 0.f;

    int jp = tid & 63;   // 0..63 -> hidden unit pair
    int mg = tid >> 6;   // 0..7  -> entity group of 4
    int j0 = jp << 1;
    int m0 = mg << 2;

    float c[8], hn[8];
#pragma unroll
    for (int i = 0; i < 8; i++) { c[i] = 0.f; hn[i] = 0.f; }

    const float4* Wd4 = (const float4*)(g_WhhI + dir * 128 * 512);
    const float* xd = g_xgI + dir * 25 * 512;
    __syncthreads();

    float4 pre[4];
    for (int step = 0; step < MAXDEG_; step++) {
        float acc[4][8];
#pragma unroll
        for (int m = 0; m < 4; m++)
#pragma unroll
            for (int q = 0; q < 8; q++) acc[m][q] = 0.f;

        // stage chunk 0 (16 k-rows of WhhI)
#pragma unroll
        for (int p = 0; p < 4; p++) pre[p] = Wd4[p * 512 + tid];
#pragma unroll
        for (int p = 0; p < 4; p++) ((float4*)sB)[p * 512 + tid] = pre[p];
        __syncthreads();

        for (int chunk = 0; chunk < 8; chunk++) {
            const float* buf = sB + (chunk & 1) * 8192;
            if (chunk < 7) {
#pragma unroll
                for (int p = 0; p < 4; p++)
                    pre[p] = Wd4[(chunk + 1) * 2048 + p * 512 + tid];
            }
#pragma unroll
            for (int kk = 0; kk < 16; kk++) {
                int k = chunk * 16 + kk;
                float4 a  = *(const float4*)&sh[k * SH_PITCH + m0];
                float4 b0 = *(const float4*)&buf[kk * 512 + j0 * 4];
                float4 b1 = *(const float4*)&buf[kk * 512 + j0 * 4 + 4];
                float aa[4] = {a.x, a.y, a.z, a.w};
                float bb[8] = {b0.x, b0.y, b0.z, b0.w, b1.x, b1.y, b1.z, b1.w};
#pragma unroll
                for (int m = 0; m < 4; m++)
#pragma unroll
                    for (int q = 0; q < 8; q++) acc[m][q] += aa[m] * bb[q];
            }
            __syncthreads();
            if (chunk < 7) {
                float* nb = sB + ((chunk + 1) & 1) * 8192;
#pragma unroll
                for (int p = 0; p < 4; p++) ((float4*)nb)[p * 512 + tid] = pre[p];
                __syncthreads();
            }
        }

        // gate nonlinearities (per-thread private c)
#pragma unroll
        for (int m = 0; m < 4; m++) {
            int d = sdeg[(m0 + m) * MAXDEG_ + step];
            const float4* xb = (const float4*)&xd[d * 512 + j0 * 4];
#pragma unroll
            for (int jj = 0; jj < 2; jj++) {
                float4 xv = xb[jj];
                float iv = acc[m][jj * 4 + 0] + xv.x;
                float fv = acc[m][jj * 4 + 1] + xv.y;
                float gv = acc[m][jj * 4 + 2] + xv.z;
                float ov = acc[m][jj * 4 + 3] + xv.w;
                int ci = m * 2 + jj;
                c[ci] = sigm(fv) * c[ci] + sigm(iv) * tanhf(gv);
                hn[ci] = sigm(ov) * tanhf(c[ci]);
            }
        }
        // all reads of old h finished (barrier after last chunk); publish new h
#pragma unroll
        for (int m = 0; m < 4; m++) {
            sh[j0 * SH_PITCH + m0 + m]       = hn[m * 2 + 0];
            sh[(j0 + 1) * SH_PITCH + m0 + m] = hn[m * 2 + 1];
        }
        __syncthreads();
    }

    // write final hidden state (only thing needed downstream)
#pragma unroll
    for (int m = 0; m < 4; m++) {
        int n = n0 + m0 + m;
        if (n < N_) {
            g_eh[n * 256 + dir * 128 + j0]     = hn[m * 2 + 0];
            g_eh[n * 256 + dir * 128 + j0 + 1] = hn[m * 2 + 1];
        }
    }
}

// ---------------- entity attention softmax: warp per entity ----------------------
__global__ void k_eattn(const float* __restrict__ e_lin_W, const float* __restrict__ e_lin_b) {
    int warp = (blockIdx.x * blockDim.x + threadIdx.x) >> 5;
    int lane = threadIdx.x & 31;
    if (warp >= N_) return;
    int n = warp;
    float s = -1e30f;
    if (lane < OPS_) {
        s = e_lin_b[lane];
        const float4* h4 = (const float4*)(g_eh + n * 256);
        const float4* w4 = (const float4*)(e_lin_W + lane * 256);
#pragma unroll 4
        for (int k = 0; k < 64; k++) {
            float4 hh = h4[k], ww = w4[k];
            s += hh.x * ww.x + hh.y * ww.y + hh.z * ww.z + hh.w * ww.w;
        }
    }
    float mx = s;
    for (int o = 16; o; o >>= 1) mx = fmaxf(mx, __shfl_xor_sync(0xffffffffu, mx, o));
    float e = (lane < OPS_) ? expf(s - mx) : 0.f;
    float sum = e;
    for (int o = 16; o; o >>= 1) sum += __shfl_xor_sync(0xffffffffu, sum, o);
    if (lane < OPS_) g_attn[n * OPS_ + lane] = e / sum;
}

// ---------------- per-edge weight gather -----------------------------------------
__global__ void k_w(const int* __restrict__ rels, const int* __restrict__ t_heads) {
    int e = blockIdx.x * blockDim.x + threadIdx.x;
    if (e < E_) g_w[e] = g_attn[t_heads[e] * OPS_ + rels[e]];
}

// ---------------- query BiLSTM: one warp per (r, dir, b) -------------------------
__global__ void k_qlstm(const int* __restrict__ queries, const float* __restrict__ q_emb,
                        const float* __restrict__ q_Wih, const float* __restrict__ q_Whh,
                        const float* __restrict__ q_bih, const float* __restrict__ q_bhh) {
    int w = (blockIdx.x * blockDim.x + threadIdx.x) >> 5;
    int lane = threadIdx.x & 31;
    if (w >= R_ * 2 * B_) return;
    int b = w & 31;
    int dir = (w >> 5) & 1;
    int r = w >> 6;
    int rd = r * 2 + dir;

    const float* x = q_emb + queries[b] * QD_;
    const float* Wih = q_Wih + rd * 512 * 128;
    const float* Whh = q_Whh + rd * 512 * 128;
    const float* bih = q_bih + rd * 512;
    const float* bhh = q_bhh + rd * 512;

    float xw[4][4];
#pragma unroll
    for (int g = 0; g < 4; g++)
#pragma unroll
        for (int s = 0; s < 4; s++) {
            int row = g * 128 + lane + 32 * s;
            float acc = bih[row] + bhh[row];
            const float* wr = Wih + row * 128;
            for (int k = 0; k < 128; k++) acc += x[k] * wr[k];
            xw[g][s] = acc;
        }

    float h[4] = {0, 0, 0, 0}, c4[4] = {0, 0, 0, 0};
    for (int t = 0; t < T_; t++) {
        float gg[4][4];
#pragma unroll
        for (int g = 0; g < 4; g++)
#pragma unroll
            for (int s = 0; s < 4; s++) gg[g][s] = xw[g][s];
        for (int k = 0; k < 128; k++) {
            float hk = __shfl_sync(0xffffffffu, h[k >> 5], k & 31);
#pragma unroll
            for (int g = 0; g < 4; g++)
#pragma unroll
                for (int s = 0; s < 4; s++)
                    gg[g][s] += hk * Whh[(g * 128 + lane + 32 * s) * 128 + k];
        }
#pragma unroll
        for (int s = 0; s < 4; s++) {
            float iv = gg[0][s], fv = gg[1][s], gv = gg[2][s], ov = gg[3][s];
            c4[s] = sigm(fv) * c4[s] + sigm(iv) * tanhf(gv);
            h[s] = sigm(ov) * tanhf(c4[s]);
        }
#pragma unroll
        for (int s = 0; s < 4; s++)
            g_qys[((rd * 3 + t) * B_ + b) * H_ + lane + 32 * s] = h[s];
    }
}

// ---------------- query attention softmax: warp per (r,t,b) ----------------------
__global__ void k_qattn(const float* __restrict__ q_lin_W, const float* __restrict__ q_lin_b) {
    int w = (blockIdx.x * blockDim.x + threadIdx.x) >> 5;
    int lane = threadIdx.x & 31;
    if (w >= R_ * T_ * B_) return;
    int b = w & 31;
    int t = (w >> 5) % 3;
    int r = w / (3 * 32);
    const float* ysf = g_qys + (((r * 2 + 0) * 3 + t) * B_ + b) * H_;
    const float* ysb = g_qys + (((r * 2 + 1) * 3 + (2 - t)) * B_ + b) * H_;
    float s = -1e30f;
    if (lane <= OPS_) {  // 25 lanes active
        s = q_lin_b[lane];
        const float* wv = q_lin_W + lane * 256;
        for (int k = 0; k < 128; k++) s += ysf[k] * wv[k];
        for (int k = 0; k < 128; k++) s += ysb[k] * wv[128 + k];
    }
    float mx = s;
    for (int o = 16; o; o >>= 1) mx = fmaxf(mx, __shfl_xor_sync(0xffffffffu, mx, o));
    float e = (lane <= OPS_) ? expf(s - mx) : 0.f;
    float sum = e;
    for (int o = 16; o; o >>= 1) sum += __shfl_xor_sync(0xffffffffu, sum, o);
    if (lane <= OPS_)
        g_qaT[((r * 3 + t) * (OPS_ + 1) + lane) * B_ + b] = e / sum;
}

// ---------------- propagation kernels --------------------------------------------
__global__ void k_seed(const int* __restrict__ heads) {
    int b = threadIdx.x;
    if (b < B_) g_mem[heads[b] * B_ + b] = 1.f;
}

__global__ void k_edge(const int* __restrict__ rels, const int* __restrict__ t_heads,
                       const int* __restrict__ t_tails, int rt) {
    __shared__ float qs[(OPS_ + 1) * B_];
    int tid = threadIdx.x;
    const float* qsrc = g_qaT + rt * (OPS_ + 1) * B_;
    for (int i = tid; i < (OPS_ + 1) * B_; i += blockDim.x) qs[i] = qsrc[i];
    __syncthreads();
    int lane = tid & 31;
    int warp = (blockIdx.x * blockDim.x + tid) >> 5;
    int nw = (gridDim.x * blockDim.x) >> 5;
    for (int e = warp; e < E_; e += nw) {
        int rel = rels[e], hd = t_heads[e], tl = t_tails[e];
        float we = g_w[e];
        float fwd = qs[rel * B_ + lane] * we * g_mem[hd * B_ + lane];
        float rev = qs[(rel + OPS_ / 2) * B_ + lane] * we * g_mem[tl * B_ + lane];
        atomicAdd(&g_added[tl * B_ + lane], fwd);
        atomicAdd(&g_added[hd * B_ + lane], rev);
    }
}

__global__ void k_self(int rt) {
    __shared__ float red[8][32];
    int tid = threadIdx.x;
    int lane = tid & 31, rg = tid >> 5;
    float qlast = g_qaT[(rt * (OPS_ + 1) + OPS_) * B_ + lane];
    float local = 0.f;
    for (int n = blockIdx.x * 8 + rg; n < N_; n += gridDim.x * 8) {
        int i = n * B_ + lane;
        float v = g_added[i] + g_mem[i] * qlast;
        g_added[i] = v;
        local += v;
    }
    red[rg][lane] = local;
    __syncthreads();
    if (rg == 0) {
        float s = 0.f;
#pragma unroll
        for (int q = 0; q < 8; q++) s += red[q][lane];
        atomicAdd(&g_gsum[lane], s);
    }
}

__global__ void k_norm() {
    int i = blockIdx.x * blockDim.x + threadIdx.x;
    if (i < N_ * B_) {
        float d = g_gsum[i & 31];
        g_mem[i] = g_added[i] / fmaxf(1e-20f, d);
    }
}

__global__ void k_accum(float* __restrict__ out) {
    int i = blockIdx.x * blockDim.x + threadIdx.x;
    if (i < N_ * B_) {
        int b = i / N_;
        int n = i - b * N_;
        out[i] += g_mem[n * B_ + b];
    }
}

// ---------------- host launch ----------------------------------------------------
extern "C" void kernel_launch(void* const* d_in, const int* in_sizes, int n_in,
                              void* d_out, int out_size) {
    const int* queries   = (const int*)d_in[0];
    const int* heads     = (const int*)d_in[1];
    const int* rels      = (const int*)d_in[2];
    const int* t_heads   = (const int*)d_in[3];
    const int* t_tails   = (const int*)d_in[4];
    const int* degrees   = (const int*)d_in[5];
    const float* q_emb   = (const float*)d_in[6];
    const float* ent_emb = (const float*)d_in[7];
    const float* q_Wih   = (const float*)d_in[8];
    const float* q_Whh   = (const float*)d_in[9];
    const float* q_bih   = (const float*)d_in[10];
    const float* q_bhh   = (const float*)d_in[11];
    const float* e_Wih   = (const float*)d_in[12];
    const float* e_Whh   = (const float*)d_in[13];
    const float* e_bih   = (const float*)d_in[14];
    const float* e_bhh   = (const float*)d_in[15];
    const float* q_lin_W = (const float*)d_in[16];
    const float* q_lin_b = (const float*)d_in[17];
    const float* e_lin_W = (const float*)d_in[18];
    const float* e_lin_b = (const float*)d_in[19];
    float* out = (float*)d_out;

    void *p_mem, *p_added, *p_gsum;
    cudaGetSymbolAddress(&p_mem, g_mem);
    cudaGetSymbolAddress(&p_added, g_added);
    cudaGetSymbolAddress(&p_gsum, g_gsum);

    cudaMemsetAsync(d_out, 0, (size_t)N_ * B_ * sizeof(float));

    // precompute
    k_xg<<<dim3(25, 2), 512>>>(ent_emb, e_Wih, e_bih, e_bhh);
    k_whhT<<<dim3(128, 2), 512>>>(e_Whh);

    // entity BiLSTM (dominant)
    size_t smem = (size_t)(2 * 16 * 512 + 128 * SH_PITCH) * sizeof(float) +
                  (size_t)TILE_M * MAXDEG_ * sizeof(int);
    cudaFuncSetAttribute(k_entity, cudaFuncAttributeMaxDynamicSharedMemorySize, (int)smem);
    k_entity<<<dim3((N_ + TILE_M - 1) / TILE_M, 2), EK_THREADS, smem>>>(degrees);

    k_eattn<<<(N_ * 32 + 255) / 256, 256>>>(e_lin_W, e_lin_b);
    k_w<<<(E_ + 255) / 256, 256>>>(rels, t_heads);

    // query path
    k_qlstm<<<24, 256>>>(queries, q_emb, q_Wih, q_Whh, q_bih, q_bhh);
    k_qattn<<<36, 256>>>(q_lin_W, q_lin_b);

    // propagation
    for (int r = 0; r < R_; r++) {
        cudaMemsetAsync(p_mem, 0, (size_t)N_ * B_ * sizeof(float));
        k_seed<<<1, 32>>>(heads);
        for (int t = 0; t < T_; t++) {
            int rt = r * 3 + t;
            cudaMemsetAsync(p_added, 0, (size_t)N_ * B_ * sizeof(float));
            cudaMemsetAsync(p_gsum, 0, B_ * sizeof(float));
            k_edge<<<2048, 256>>>(rels, t_heads, t_tails, rt);
            k_self<<<256, 256>>>(rt);
            k_norm<<<(N_ * B_ + 255) / 256, 256>>>();
        }
        k_accum<<<(N_ * B_ + 255) / 256, 256>>>(out);
    }
}

// round 5
// speedup vs baseline: 2.0863x; 2.0863x over previous
#include <cuda_runtime.h>
#include <math.h>

#define R_ 3
#define T_ 3
#define N_ 50000
#define OPS_ 24
#define E_ 400000
#define B_ 32
#define MAXDEG_ 8
#define QD_ 128
#define H_ 128

// ---------------- device scratch ----------------
__device__ float g_xgI[2 * 25 * 512];         // [dir][d][j*4+g]
__device__ float g_Wt[2 * 128 * 512];         // tf32-rounded Whh, [dir][k][j*4+g]
__device__ float g_eh[N_ * 256];
__device__ float g_attn[N_ * OPS_];
__device__ float g_w[E_];
__device__ float g_qys[R_ * 2 * T_ * B_ * H_];
__device__ float g_qaT[R_ * T_ * (OPS_ + 1) * B_];
__device__ float g_mem[N_ * B_];
__device__ float g_added[N_ * B_];
__device__ float g_gsum[B_];

__device__ __forceinline__ float sigm(float x) { return 1.f / (1.f + expf(-x)); }
__device__ __forceinline__ float tanh_fast(float x) {
    float y; asm("tanh.approx.f32 %0, %1;" : "=f"(y) : "f"(x)); return y;
}
__device__ __forceinline__ float sigm_fast(float x) { return 0.5f + 0.5f * tanh_fast(0.5f * x); }
__device__ __forceinline__ unsigned f2tf32(float x) {
    unsigned y; asm("cvt.rna.tf32.f32 %0, %1;" : "=r"(y) : "f"(x)); return y;
}
__device__ __forceinline__ void cpa16(float* dst, const float* src) {
    unsigned d = (unsigned)__cvta_generic_to_shared(dst);
    asm volatile("cp.async.ca.shared.global [%0], [%1], 16;" :: "r"(d), "l"(src));
}
__device__ __forceinline__ void mma8(float* c, unsigned a0, unsigned a1, unsigned a2,
                                     unsigned a3, unsigned b0, unsigned b1) {
    asm volatile("mma.sync.aligned.m16n8k8.row.col.f32.tf32.tf32.f32 "
                 "{%0,%1,%2,%3},{%4,%5,%6,%7},{%8,%9},{%0,%1,%2,%3};"
                 : "+f"(c[0]), "+f"(c[1]), "+f"(c[2]), "+f"(c[3])
                 : "r"(a0), "r"(a1), "r"(a2), "r"(a3), "r"(b0), "r"(b1));
}

// ---------------- xg[dir][d][j*4+g] = emb[d]@Wih^T + bih + bhh ----------------
__global__ void k_xg(const float* __restrict__ ent_emb, const float* __restrict__ e_Wih,
                     const float* __restrict__ e_bih, const float* __restrict__ e_bhh) {
    int d = blockIdx.x, dir = blockIdx.y, tid = threadIdx.x;
    int j = tid >> 2, g = tid & 3;
    int row = g * 128 + j;
    const float* w = e_Wih + (dir * 512 + row) * 128;
    const float* x = ent_emb + d * 128;
    float s = e_bih[dir * 512 + row] + e_bhh[dir * 512 + row];
    for (int k = 0; k < 128; k++) s += x[k] * w[k];
    g_xgI[(dir * 25 + d) * 512 + tid] = s;
}

// ---------------- Wt[dir][k][j*4+g] = tf32(Whh[dir][g*128+j][k]) ---------------
__global__ void k_whhT(const float* __restrict__ e_Whh) {
    int k = blockIdx.x, dir = blockIdx.y, tid = threadIdx.x;
    int j = tid >> 2, g = tid & 3;
    float v = e_Whh[(dir * 512 + g * 128 + j) * 128 + k];
    g_Wt[(dir * 128 + k) * 512 + tid] = __uint_as_float(f2tf32(v));
}

// ---------------- entity BiLSTM: tf32 tensor-core kernel -----------------------
// smem floats: hsm 64*132 | bsm 2*16*516 | xsm 25*516 | sdeg 512 ints
#define HSM 0
#define BSM 8448
#define XSM 24960
#define SDG 37860
#define ESMEM (38372 * 4)

__global__ void __launch_bounds__(512, 1) k_entity2(const int* __restrict__ degrees) {
    extern __shared__ float sm[];
    float* hsm = sm + HSM;
    float* bsm = sm + BSM;
    float* xsm = sm + XSM;
    int* sdeg = (int*)(sm + SDG);

    const int tid = threadIdx.x, lane = tid & 31, wid = tid >> 5;
    const int dir = blockIdx.y;
    const int n0 = blockIdx.x * 64;

    const float* xg = g_xgI + dir * 25 * 512;
    for (int i = tid; i < 25 * 512; i += 512)
        xsm[(i >> 9) * 516 + (i & 511)] = xg[i];
    {
        int row = tid >> 3, t = tid & 7, n = n0 + row;
        sdeg[tid] = (n < N_) ? degrees[n * 8 + (dir ? 7 - t : t)] : 0;
    }
    __syncthreads();

    const float* Wt = g_Wt + dir * 128 * 512;
    const int skr = tid >> 5, soff = (tid & 31) * 16;  // staging: k-row, float offset

    float cst[16];
#pragma unroll
    for (int i = 0; i < 16; i++) cst[i] = 0.f;

    for (int step = 0; step < 8; step++) {
        float acc[4][4][4];
#pragma unroll
        for (int mf = 0; mf < 4; mf++)
#pragma unroll
            for (int nf = 0; nf < 4; nf++)
#pragma unroll
                for (int q = 0; q < 4; q++) acc[mf][nf][q] = 0.f;

        if (step) {
            // stage chunk 0
            {
                float* d0 = bsm + skr * 516 + soff;
                const float* s0 = Wt + skr * 512 + soff;
#pragma unroll
                for (int q = 0; q < 4; q++) cpa16(d0 + q * 4, s0 + q * 4);
                asm volatile("cp.async.commit_group;");
            }
            for (int ch = 0; ch < 8; ch++) {
                if (ch < 7) {
                    float* d0 = bsm + ((ch + 1) & 1) * 8256 + skr * 516 + soff;
                    const float* s0 = Wt + ((ch + 1) * 16 + skr) * 512 + soff;
#pragma unroll
                    for (int q = 0; q < 4; q++) cpa16(d0 + q * 4, s0 + q * 4);
                    asm volatile("cp.async.commit_group;");
                    asm volatile("cp.async.wait_group 1;");
                } else {
                    asm volatile("cp.async.wait_group 0;");
                }
                __syncthreads();
                const float* bf = bsm + (ch & 1) * 8256;
#pragma unroll
                for (int sub = 0; sub < 2; sub++) {
                    int kb = ch * 16 + sub * 8;
                    int kl = sub * 8 + (lane & 3);
                    unsigned b0[4], b1[4];
#pragma unroll
                    for (int nf = 0; nf < 4; nf++) {
                        int col = wid * 32 + nf * 8 + (lane >> 2);
                        b0[nf] = __float_as_uint(bf[kl * 516 + col]);
                        b1[nf] = __float_as_uint(bf[(kl + 4) * 516 + col]);
                    }
#pragma unroll
                    for (int mf = 0; mf < 4; mf++) {
                        const float* ap = hsm + (mf * 16 + (lane >> 2)) * 132 + kb + (lane & 3);
                        unsigned a0 = __float_as_uint(ap[0]);
                        unsigned a1 = __float_as_uint(ap[8 * 132]);
                        unsigned a2 = __float_as_uint(ap[4]);
                        unsigned a3 = __float_as_uint(ap[8 * 132 + 4]);
#pragma unroll
                        for (int nf = 0; nf < 4; nf++)
                            mma8(acc[mf][nf], a0, a1, a2, a3, b0[nf], b1[nf]);
                    }
                }
                __syncthreads();
            }
        }

        // epilogue: pair-exchange gates, LSTM cell, write tf32 h
        int par = lane & 1;
#pragma unroll
        for (int mf = 0; mf < 4; mf++)
#pragma unroll
            for (int nf = 0; nf < 4; nf++) {
                float* a = acc[mf][nf];
                float x0 = __shfl_xor_sync(~0u, par ? a[0] : a[2], 1);
                float x1 = __shfl_xor_sync(~0u, par ? a[1] : a[3], 1);
                int row = mf * 16 + (lane >> 2) + 8 * par;
                int u = wid * 8 + nf * 2 + ((lane & 3) >> 1);
                int d = sdeg[row * 8 + step];
                float4 xv = *(const float4*)&xsm[d * 516 + u * 4];
                float iv, fv, gv, ov;
                if (par) { iv = x0; fv = x1; gv = a[2]; ov = a[3]; }
                else     { iv = a[0]; fv = a[1]; gv = x0; ov = x1; }
                iv += xv.x; fv += xv.y; gv += xv.z; ov += xv.w;
                float c = cst[mf * 4 + nf];
                c = sigm_fast(fv) * c + sigm_fast(iv) * tanh_fast(gv);
                cst[mf * 4 + nf] = c;
                float h = sigm_fast(ov) * tanh_fast(c);
                if (step < 7) {
                    hsm[row * 132 + u] = __uint_as_float(f2tf32(h));
                } else {
                    int n = n0 + row;
                    if (n < N_) g_eh[n * 256 + dir * 128 + u] = h;
                }
            }
        __syncthreads();
    }
}

// ---------------- entity attention: smem weights, butterfly reduce -------------
__global__ void k_eattn(const float* __restrict__ e_lin_W, const float* __restrict__ e_lin_b) {
    __shared__ float sw[24 * 256];
    __shared__ float sb[24];
    int tid = threadIdx.x;
    for (int i = tid; i < 24 * 256; i += 256) sw[i] = e_lin_W[i];
    if (tid < 24) sb[tid] = e_lin_b[tid];
    __syncthreads();
    int lane = tid & 31;
    for (int n = blockIdx.x * 8 + (tid >> 5); n < N_; n += gridDim.x * 8) {
        float h[8];
        const float* hp = g_eh + n * 256;
#pragma unroll
        for (int j = 0; j < 8; j++) h[j] = hp[lane + 32 * j];
        float mine = -1e30f;
#pragma unroll
        for (int op = 0; op < 24; op++) {
            const float* wp = sw + op * 256 + lane;
            float s = 0.f;
#pragma unroll
            for (int j = 0; j < 8; j++) s += h[j] * wp[32 * j];
            for (int o = 16; o; o >>= 1) s += __shfl_xor_sync(~0u, s, o);
            if (lane == op) mine = s + sb[op];
        }
        float mx = mine;
        for (int o = 16; o; o >>= 1) mx = fmaxf(mx, __shfl_xor_sync(~0u, mx, o));
        float e = (lane < 24) ? expf(mine - mx) : 0.f;
        float sum = e;
        for (int o = 16; o; o >>= 1) sum += __shfl_xor_sync(~0u, sum, o);
        if (lane < 24) g_attn[n * 24 + lane] = e / sum;
    }
}

__global__ void k_w(const int* __restrict__ rels, const int* __restrict__ t_heads) {
    int e = blockIdx.x * blockDim.x + threadIdx.x;
    if (e < E_) g_w[e] = g_attn[t_heads[e] * OPS_ + rels[e]];
}

// ---------------- query BiLSTM + attention (tiny) ------------------------------
__global__ void k_qlstm(const int* __restrict__ queries, const float* __restrict__ q_emb,
                        const float* __restrict__ q_Wih, const float* __restrict__ q_Whh,
                        const float* __restrict__ q_bih, const float* __restrict__ q_bhh) {
    int w = (blockIdx.x * blockDim.x + threadIdx.x) >> 5;
    int lane = threadIdx.x & 31;
    if (w >= R_ * 2 * B_) return;
    int b = w & 31, dir = (w >> 5) & 1, r = w >> 6;
    int rd = r * 2 + dir;
    const float* x = q_emb + queries[b] * QD_;
    const float* Wih = q_Wih + rd * 512 * 128;
    const float* Whh = q_Whh + rd * 512 * 128;
    float xw[4][4];
#pragma unroll
    for (int g = 0; g < 4; g++)
#pragma unroll
        for (int s = 0; s < 4; s++) {
            int row = g * 128 + lane + 32 * s;
            float acc = q_bih[rd * 512 + row] + q_bhh[rd * 512 + row];
            const float* wr = Wih + row * 128;
            for (int k = 0; k < 128; k++) acc += x[k] * wr[k];
            xw[g][s] = acc;
        }
    float h[4] = {0, 0, 0, 0}, c4[4] = {0, 0, 0, 0};
    for (int t = 0; t < T_; t++) {
        float gg[4][4];
#pragma unroll
        for (int g = 0; g < 4; g++)
#pragma unroll
            for (int s = 0; s < 4; s++) gg[g][s] = xw[g][s];
        for (int k = 0; k < 128; k++) {
            float hk = __shfl_sync(~0u, h[k >> 5], k & 31);
#pragma unroll
            for (int g = 0; g < 4; g++)
#pragma unroll
                for (int s = 0; s < 4; s++)
                    gg[g][s] += hk * Whh[(g * 128 + lane + 32 * s) * 128 + k];
        }
#pragma unroll
        for (int s = 0; s < 4; s++) {
            c4[s] = sigm(gg[1][s]) * c4[s] + sigm(gg[0][s]) * tanhf(gg[2][s]);
            h[s] = sigm(gg[3][s]) * tanhf(c4[s]);
        }
#pragma unroll
        for (int s = 0; s < 4; s++)
            g_qys[((rd * 3 + t) * B_ + b) * H_ + lane + 32 * s] = h[s];
    }
}

__global__ void k_qattn(const float* __restrict__ q_lin_W, const float* __restrict__ q_lin_b) {
    int w = (blockIdx.x * blockDim.x + threadIdx.x) >> 5;
    int lane = threadIdx.x & 31;
    if (w >= R_ * T_ * B_) return;
    int b = w & 31, t = (w >> 5) % 3, r = w / 96;
    const float* ysf = g_qys + (((r * 2 + 0) * 3 + t) * B_ + b) * H_;
    const float* ysb = g_qys + (((r * 2 + 1) * 3 + (2 - t)) * B_ + b) * H_;
    float s = -1e30f;
    if (lane <= OPS_) {
        s = q_lin_b[lane];
        const float* wv = q_lin_W + lane * 256;
        for (int k = 0; k < 128; k++) s += ysf[k] * wv[k];
        for (int k = 0; k < 128; k++) s += ysb[k] * wv[128 + k];
    }
    float mx = s;
    for (int o = 16; o; o >>= 1) mx = fmaxf(mx, __shfl_xor_sync(~0u, mx, o));
    float e = (lane <= OPS_) ? expf(s - mx) : 0.f;
    float sum = e;
    for (int o = 16; o; o >>= 1) sum += __shfl_xor_sync(~0u, sum, o);
    if (lane <= OPS_) g_qaT[((r * 3 + t) * (OPS_ + 1) + lane) * B_ + b] = e / sum;
}

// ---------------- propagation ---------------------------------------------------
__global__ void k_seed(const int* __restrict__ heads) {
    int b = threadIdx.x;
    if (b < B_) g_mem[heads[b] * B_ + b] = 1.f;
}

__global__ void k_edge(const int* __restrict__ rels, const int* __restrict__ t_heads,
                       const int* __restrict__ t_tails, int rt) {
    __shared__ float qs[(OPS_ + 1) * B_];
    int tid = threadIdx.x;
    const float* qsrc = g_qaT + rt * (OPS_ + 1) * B_;
    for (int i = tid; i < (OPS_ + 1) * B_; i += blockDim.x) qs[i] = qsrc[i];
    __syncthreads();
    int lane = tid & 31;
    int warp = (blockIdx.x * blockDim.x + tid) >> 5;
    int nw = (gridDim.x * blockDim.x) >> 5;
    for (int e = warp; e < E_; e += nw) {
        int rel = rels[e], hd = t_heads[e], tl = t_tails[e];
        float we = g_w[e];
        float fwd = qs[rel * B_ + lane] * we * g_mem[hd * B_ + lane];
        float rev = qs[(rel + OPS_ / 2) * B_ + lane] * we * g_mem[tl * B_ + lane];
        atomicAdd(&g_added[tl * B_ + lane], fwd);
        atomicAdd(&g_added[hd * B_ + lane], rev);
    }
}

__global__ void k_self(int rt) {
    __shared__ float red[8][32];
    int tid = threadIdx.x;
    int lane = tid & 31, rg = tid >> 5;
    float qlast = g_qaT[(rt * (OPS_ + 1) + OPS_) * B_ + lane];
    float local = 0.f;
    for (int n = blockIdx.x * 8 + rg; n < N_; n += gridDim.x * 8) {
        int i = n * B_ + lane;
        float v = g_added[i] + g_mem[i] * qlast;
        g_added[i] = v;
        local += v;
    }
    red[rg][lane] = local;
    __syncthreads();
    if (rg == 0) {
        float s = 0.f;
#pragma unroll
        for (int q = 0; q < 8; q++) s += red[q][lane];
        atomicAdd(&g_gsum[lane], s);
    }
}

__global__ void k_norm() {
    int i = blockIdx.x * blockDim.x + threadIdx.x;
    if (i < N_ * B_) g_mem[i] = g_added[i] / fmaxf(1e-20f, g_gsum[i & 31]);
}

__global__ void k_accum(float* __restrict__ out) {
    int i = blockIdx.x * blockDim.x + threadIdx.x;
    if (i < N_ * B_) {
        int b = i / N_, n = i - b * N_;
        out[i] += g_mem[n * B_ + b];
    }
}

// ---------------- host ----------------------------------------------------------
extern "C" void kernel_launch(void* const* d_in, const int* in_sizes, int n_in,
                              void* d_out, int out_size) {
    const int* queries   = (const int*)d_in[0];
    const int* heads     = (const int*)d_in[1];
    const int* rels      = (const int*)d_in[2];
    const int* t_heads   = (const int*)d_in[3];
    const int* t_tails   = (const int*)d_in[4];
    const int* degrees   = (const int*)d_in[5];
    const float* q_emb   = (const float*)d_in[6];
    const float* ent_emb = (const float*)d_in[7];
    const float* q_Wih   = (const float*)d_in[8];
    const float* q_Whh   = (const float*)d_in[9];
    const float* q_bih   = (const float*)d_in[10];
    const float* q_bhh   = (const float*)d_in[11];
    const float* e_Wih   = (const float*)d_in[12];
    const float* e_Whh   = (const float*)d_in[13];
    const float* e_bih   = (const float*)d_in[14];
    const float* e_bhh   = (const float*)d_in[15];
    const float* q_lin_W = (const float*)d_in[16];
    const float* q_lin_b = (const float*)d_in[17];
    const float* e_lin_W = (const float*)d_in[18];
    const float* e_lin_b = (const float*)d_in[19];
    float* out = (float*)d_out;

    void *p_mem, *p_added, *p_gsum;
    cudaGetSymbolAddress(&p_mem, g_mem);
    cudaGetSymbolAddress(&p_added, g_added);
    cudaGetSymbolAddress(&p_gsum, g_gsum);

    cudaMemsetAsync(d_out, 0, (size_t)N_ * B_ * sizeof(float));

    k_xg<<<dim3(25, 2), 512>>>(ent_emb, e_Wih, e_bih, e_bhh);
    k_whhT<<<dim3(128, 2), 512>>>(e_Whh);

    cudaFuncSetAttribute(k_entity2, cudaFuncAttributeMaxDynamicSharedMemorySize, ESMEM);
    k_entity2<<<dim3((N_ + 63) / 64, 2), 512, ESMEM>>>(degrees);

    k_eattn<<<782, 256>>>(e_lin_W, e_lin_b);
    k_w<<<(E_ + 255) / 256, 256>>>(rels, t_heads);

    k_qlstm<<<24, 256>>>(queries, q_emb, q_Wih, q_Whh, q_bih, q_bhh);
    k_qattn<<<36, 256>>>(q_lin_W, q_lin_b);

    for (int r = 0; r < R_; r++) {
        cudaMemsetAsync(p_mem, 0, (size_t)N_ * B_ * sizeof(float));
        k_seed<<<1, 32>>>(heads);
        for (int t = 0; t < T_; t++) {
            int rt = r * 3 + t;
            cudaMemsetAsync(p_added, 0, (size_t)N_ * B_ * sizeof(float));
            cudaMemsetAsync(p_gsum, 0, B_ * sizeof(float));
            k_edge<<<2048, 256>>>(rels, t_heads, t_tails, rt);
            k_self<<<256, 256>>>(rt);
            k_norm<<<(N_ * B_ + 255) / 256, 256>>>();
        }
        k_accum<<<(N_ * B_ + 255) / 256, 256>>>(out);
    }
}

// round 6
// speedup vs baseline: 2.1528x; 1.0319x over previous
#include <cuda_runtime.h>
#include <math.h>

#define R_ 3
#define T_ 3
#define N_ 50000
#define OPS_ 24
#define E_ 400000
#define B_ 32
#define MAXDEG_ 8
#define QD_ 128
#define H_ 128

// ---------------- device scratch ----------------
__device__ float g_xgI[2 * 25 * 512];
__device__ float g_Wt[2 * 128 * 512];
__device__ float g_eh[N_ * 256];
__device__ float g_attn[N_ * OPS_];
__device__ float g_w[E_];
__device__ float g_qys[R_ * 2 * T_ * B_ * H_];
__device__ float g_qaT[R_ * T_ * (OPS_ + 1) * B_];
__device__ float g_memA[N_ * B_];
__device__ float g_memB[N_ * B_];
__device__ float g_sums[R_ * T_ * B_];
// CSR (by destination node): 2E entries
__device__ int g_deg[N_];
__device__ int g_rowptr[N_ + 1];
__device__ int g_cursor[N_];
__device__ int g_csrp[2 * E_];    // (src<<5) | relidx
__device__ float g_csrw[2 * E_];

__device__ __forceinline__ float sigm(float x) { return 1.f / (1.f + expf(-x)); }
__device__ __forceinline__ float tanh_fast(float x) {
    float y; asm("tanh.approx.f32 %0, %1;" : "=f"(y) : "f"(x)); return y;
}
__device__ __forceinline__ float sigm_fast(float x) { return 0.5f + 0.5f * tanh_fast(0.5f * x); }
__device__ __forceinline__ unsigned f2tf32(float x) {
    unsigned y; asm("cvt.rna.tf32.f32 %0, %1;" : "=r"(y) : "f"(x)); return y;
}
__device__ __forceinline__ void cpa16(float* dst, const float* src) {
    unsigned d = (unsigned)__cvta_generic_to_shared(dst);
    asm volatile("cp.async.ca.shared.global [%0], [%1], 16;" :: "r"(d), "l"(src));
}
__device__ __forceinline__ void mma8(float* c, unsigned a0, unsigned a1, unsigned a2,
                                     unsigned a3, unsigned b0, unsigned b1) {
    asm volatile("mma.sync.aligned.m16n8k8.row.col.f32.tf32.tf32.f32 "
                 "{%0,%1,%2,%3},{%4,%5,%6,%7},{%8,%9},{%0,%1,%2,%3};"
                 : "+f"(c[0]), "+f"(c[1]), "+f"(c[2]), "+f"(c[3])
                 : "r"(a0), "r"(a1), "r"(a2), "r"(a3), "r"(b0), "r"(b1));
}

// ---------------- precompute ----------------
__global__ void k_xg(const float* __restrict__ ent_emb, const float* __restrict__ e_Wih,
                     const float* __restrict__ e_bih, const float* __restrict__ e_bhh) {
    int d = blockIdx.x, dir = blockIdx.y, tid = threadIdx.x;
    int j = tid >> 2, g = tid & 3;
    int row = g * 128 + j;
    const float* w = e_Wih + (dir * 512 + row) * 128;
    const float* x = ent_emb + d * 128;
    float s = e_bih[dir * 512 + row] + e_bhh[dir * 512 + row];
    for (int k = 0; k < 128; k++) s += x[k] * w[k];
    g_xgI[(dir * 25 + d) * 512 + tid] = s;
}

__global__ void k_whhT(const float* __restrict__ e_Whh) {
    int k = blockIdx.x, dir = blockIdx.y, tid = threadIdx.x;
    int j = tid >> 2, g = tid & 3;
    float v = e_Whh[(dir * 512 + g * 128 + j) * 128 + k];
    g_Wt[(dir * 128 + k) * 512 + tid] = __uint_as_float(f2tf32(v));
}

// ---------------- CSR build ----------------
__global__ void k_deg(const int* __restrict__ t_heads, const int* __restrict__ t_tails) {
    int e = blockIdx.x * blockDim.x + threadIdx.x;
    if (e < E_) {
        atomicAdd(&g_deg[t_tails[e]], 1);
        atomicAdd(&g_deg[t_heads[e]], 1);
    }
}

__global__ void k_scan() {
    __shared__ int part[1024];
    int tid = threadIdx.x;
    int s = tid * 49, e = min(s + 49, N_);
    int sum = 0;
    for (int i = s; i < e; i++) sum += g_deg[i];
    part[tid] = sum;
    __syncthreads();
    for (int off = 1; off < 1024; off <<= 1) {
        int v = (tid >= off) ? part[tid - off] : 0;
        __syncthreads();
        part[tid] += v;
        __syncthreads();
    }
    int run = tid ? part[tid - 1] : 0;
    for (int i = s; i < e; i++) {
        g_rowptr[i] = run;
        g_cursor[i] = run;
        run += g_deg[i];
    }
    if (tid == 1023) g_rowptr[N_] = part[1023];
}

__global__ void k_fill(const int* __restrict__ rels, const int* __restrict__ t_heads,
                       const int* __restrict__ t_tails) {
    int e = blockIdx.x * blockDim.x + threadIdx.x;
    if (e >= E_) return;
    int rel = rels[e], hd = t_heads[e], tl = t_tails[e];
    float wv = g_w[e];
    int p1 = atomicAdd(&g_cursor[tl], 1);
    g_csrp[p1] = (hd << 5) | rel;
    g_csrw[p1] = wv;
    int p2 = atomicAdd(&g_cursor[hd], 1);
    g_csrp[p2] = (tl << 5) | (rel + 12);
    g_csrw[p2] = wv;
}

// ---------------- entity BiLSTM (tf32 mma) ----------------
#define HSM 0
#define BSM 8448
#define XSM 24960
#define SDG 37860
#define ESMEM (38372 * 4)

__global__ void __launch_bounds__(512, 1) k_entity2(const int* __restrict__ degrees) {
    extern __shared__ float sm[];
    float* hsm = sm + HSM;
    float* bsm = sm + BSM;
    float* xsm = sm + XSM;
    int* sdeg = (int*)(sm + SDG);

    const int tid = threadIdx.x, lane = tid & 31, wid = tid >> 5;
    const int dir = blockIdx.y;
    const int n0 = blockIdx.x * 64;

    const float* xg = g_xgI + dir * 25 * 512;
    for (int i = tid; i < 25 * 512; i += 512)
        xsm[(i >> 9) * 516 + (i & 511)] = xg[i];
    {
        int row = tid >> 3, t = tid & 7, n = n0 + row;
        sdeg[tid] = (n < N_) ? degrees[n * 8 + (dir ? 7 - t : t)] : 0;
    }
    __syncthreads();

    const float* Wt = g_Wt + dir * 128 * 512;
    const int skr = tid >> 5, soff = (tid & 31) * 16;

    float cst[16];
#pragma unroll
    for (int i = 0; i < 16; i++) cst[i] = 0.f;

    for (int step = 0; step < 8; step++) {
        float acc[4][4][4];
#pragma unroll
        for (int mf = 0; mf < 4; mf++)
#pragma unroll
            for (int nf = 0; nf < 4; nf++)
#pragma unroll
                for (int q = 0; q < 4; q++) acc[mf][nf][q] = 0.f;

        if (step) {
            {
                float* d0 = bsm + skr * 516 + soff;
                const float* s0 = Wt + skr * 512 + soff;
#pragma unroll
                for (int q = 0; q < 4; q++) cpa16(d0 + q * 4, s0 + q * 4);
                asm volatile("cp.async.commit_group;");
            }
            for (int ch = 0; ch < 8; ch++) {
                if (ch < 7) {
                    float* d0 = bsm + ((ch + 1) & 1) * 8256 + skr * 516 + soff;
                    const float* s0 = Wt + ((ch + 1) * 16 + skr) * 512 + soff;
#pragma unroll
                    for (int q = 0; q < 4; q++) cpa16(d0 + q * 4, s0 + q * 4);
                    asm volatile("cp.async.commit_group;");
                    asm volatile("cp.async.wait_group 1;");
                } else {
                    asm volatile("cp.async.wait_group 0;");
                }
                __syncthreads();
                const float* bf = bsm + (ch & 1) * 8256;
#pragma unroll
                for (int sub = 0; sub < 2; sub++) {
                    int kb = ch * 16 + sub * 8;
                    int kl = sub * 8 + (lane & 3);
                    unsigned b0[4], b1[4];
#pragma unroll
                    for (int nf = 0; nf < 4; nf++) {
                        int col = wid * 32 + nf * 8 + (lane >> 2);
                        b0[nf] = __float_as_uint(bf[kl * 516 + col]);
                        b1[nf] = __float_as_uint(bf[(kl + 4) * 516 + col]);
                    }
#pragma unroll
                    for (int mf = 0; mf < 4; mf++) {
                        const float* ap = hsm + (mf * 16 + (lane >> 2)) * 132 + kb + (lane & 3);
                        unsigned a0 = __float_as_uint(ap[0]);
                        unsigned a1 = __float_as_uint(ap[8 * 132]);
                        unsigned a2 = __float_as_uint(ap[4]);
                        unsigned a3 = __float_as_uint(ap[8 * 132 + 4]);
#pragma unroll
                        for (int nf = 0; nf < 4; nf++)
                            mma8(acc[mf][nf], a0, a1, a2, a3, b0[nf], b1[nf]);
                    }
                }
                __syncthreads();
            }
        }

        int par = lane & 1;
#pragma unroll
        for (int mf = 0; mf < 4; mf++)
#pragma unroll
            for (int nf = 0; nf < 4; nf++) {
                float* a = acc[mf][nf];
                float x0 = __shfl_xor_sync(~0u, par ? a[0] : a[2], 1);
                float x1 = __shfl_xor_sync(~0u, par ? a[1] : a[3], 1);
                int row = mf * 16 + (lane >> 2) + 8 * par;
                int u = wid * 8 + nf * 2 + ((lane & 3) >> 1);
                int d = sdeg[row * 8 + step];
                float4 xv = *(const float4*)&xsm[d * 516 + u * 4];
                float iv, fv, gv, ov;
                if (par) { iv = x0; fv = x1; gv = a[2]; ov = a[3]; }
                else     { iv = a[0]; fv = a[1]; gv = x0; ov = x1; }
                iv += xv.x; fv += xv.y; gv += xv.z; ov += xv.w;
                float c = cst[mf * 4 + nf];
                c = sigm_fast(fv) * c + sigm_fast(iv) * tanh_fast(gv);
                cst[mf * 4 + nf] = c;
                float h = sigm_fast(ov) * tanh_fast(c);
                if (step < 7) {
                    hsm[row * 132 + u] = __uint_as_float(f2tf32(h));
                } else {
                    int n = n0 + row;
                    if (n < N_) g_eh[n * 256 + dir * 128 + u] = h;
                }
            }
        __syncthreads();
    }
}

// ---------------- entity attention ----------------
__global__ void k_eattn(const float* __restrict__ e_lin_W, const float* __restrict__ e_lin_b) {
    __shared__ float sw[24 * 256];
    __shared__ float sb[24];
    int tid = threadIdx.x;
    for (int i = tid; i < 24 * 256; i += 256) sw[i] = e_lin_W[i];
    if (tid < 24) sb[tid] = e_lin_b[tid];
    __syncthreads();
    int lane = tid & 31;
    for (int n = blockIdx.x * 8 + (tid >> 5); n < N_; n += gridDim.x * 8) {
        float h[8];
        const float* hp = g_eh + n * 256;
#pragma unroll
        for (int j = 0; j < 8; j++) h[j] = hp[lane + 32 * j];
        float mine = -1e30f;
#pragma unroll
        for (int op = 0; op < 24; op++) {
            const float* wp = sw + op * 256 + lane;
            float s = 0.f;
#pragma unroll
            for (int j = 0; j < 8; j++) s += h[j] * wp[32 * j];
            for (int o = 16; o; o >>= 1) s += __shfl_xor_sync(~0u, s, o);
            if (lane == op) mine = s + sb[op];
        }
        float mx = mine;
        for (int o = 16; o; o >>= 1) mx = fmaxf(mx, __shfl_xor_sync(~0u, mx, o));
        float e = (lane < 24) ? expf(mine - mx) : 0.f;
        float sum = e;
        for (int o = 16; o; o >>= 1) sum += __shfl_xor_sync(~0u, sum, o);
        if (lane < 24) g_attn[n * 24 + lane] = e / sum;
    }
}

__global__ void k_w(const int* __restrict__ rels, const int* __restrict__ t_heads) {
    int e = blockIdx.x * blockDim.x + threadIdx.x;
    if (e < E_) g_w[e] = g_attn[t_heads[e] * OPS_ + rels[e]];
}

// ---------------- query path ----------------
__global__ void k_qlstm(const int* __restrict__ queries, const float* __restrict__ q_emb,
                        const float* __restrict__ q_Wih, const float* __restrict__ q_Whh,
                        const float* __restrict__ q_bih, const float* __restrict__ q_bhh) {
    int w = (blockIdx.x * blockDim.x + threadIdx.x) >> 5;
    int lane = threadIdx.x & 31;
    if (w >= R_ * 2 * B_) return;
    int b = w & 31, dir = (w >> 5) & 1, r = w >> 6;
    int rd = r * 2 + dir;
    const float* x = q_emb + queries[b] * QD_;
    const float* Wih = q_Wih + rd * 512 * 128;
    const float* Whh = q_Whh + rd * 512 * 128;
    float xw[4][4];
#pragma unroll
    for (int g = 0; g < 4; g++)
#pragma unroll
        for (int s = 0; s < 4; s++) {
            int row = g * 128 + lane + 32 * s;
            float acc = q_bih[rd * 512 + row] + q_bhh[rd * 512 + row];
            const float* wr = Wih + row * 128;
            for (int k = 0; k < 128; k++) acc += x[k] * wr[k];
            xw[g][s] = acc;
        }
    float h[4] = {0, 0, 0, 0}, c4[4] = {0, 0, 0, 0};
    for (int t = 0; t < T_; t++) {
        float gg[4][4];
#pragma unroll
        for (int g = 0; g < 4; g++)
#pragma unroll
            for (int s = 0; s < 4; s++) gg[g][s] = xw[g][s];
        for (int k = 0; k < 128; k++) {
            float hk = __shfl_sync(~0u, h[k >> 5], k & 31);
#pragma unroll
            for (int g = 0; g < 4; g++)
#pragma unroll
                for (int s = 0; s < 4; s++)
                    gg[g][s] += hk * Whh[(g * 128 + lane + 32 * s) * 128 + k];
        }
#pragma unroll
        for (int s = 0; s < 4; s++) {
            c4[s] = sigm(gg[1][s]) * c4[s] + sigm(gg[0][s]) * tanhf(gg[2][s]);
            h[s] = sigm(gg[3][s]) * tanhf(c4[s]);
        }
#pragma unroll
        for (int s = 0; s < 4; s++)
            g_qys[((rd * 3 + t) * B_ + b) * H_ + lane + 32 * s] = h[s];
    }
}

__global__ void k_qattn(const float* __restrict__ q_lin_W, const float* __restrict__ q_lin_b) {
    int w = (blockIdx.x * blockDim.x + threadIdx.x) >> 5;
    int lane = threadIdx.x & 31;
    if (w >= R_ * T_ * B_) return;
    int b = w & 31, t = (w >> 5) % 3, r = w / 96;
    const float* ysf = g_qys + (((r * 2 + 0) * 3 + t) * B_ + b) * H_;
    const float* ysb = g_qys + (((r * 2 + 1) * 3 + (2 - t)) * B_ + b) * H_;
    float s = -1e30f;
    if (lane <= OPS_) {
        s = q_lin_b[lane];
        const float* wv = q_lin_W + lane * 256;
        for (int k = 0; k < 128; k++) s += ysf[k] * wv[k];
        for (int k = 0; k < 128; k++) s += ysb[k] * wv[128 + k];
    }
    float mx = s;
    for (int o = 16; o; o >>= 1) mx = fmaxf(mx, __shfl_xor_sync(~0u, mx, o));
    float e = (lane <= OPS_) ? expf(s - mx) : 0.f;
    float sum = e;
    for (int o = 16; o; o >>= 1) sum += __shfl_xor_sync(~0u, sum, o);
    if (lane <= OPS_) g_qaT[((r * 3 + t) * (OPS_ + 1) + lane) * B_ + b] = e / sum;
}

// ---------------- fused propagation: gather + self + scale + reduce -------------
__global__ void __launch_bounds__(256) k_prop(const float* __restrict__ memin,
                                              float* __restrict__ memout,
                                              const int* __restrict__ heads,
                                              int rt, int rtprev) {
    __shared__ float qs[25 * 32];
    __shared__ float red[8][32];
    int tid = threadIdx.x, lane = tid & 31, wrp = tid >> 5;
    const float* qsrc = g_qaT + rt * 25 * 32;
    for (int i = tid; i < 800; i += 256) qs[i] = qsrc[i];
    __syncthreads();

    float sp = 1.f;
    int hb = -1;
    if (rtprev >= 0) sp = 1.f / fmaxf(1e-20f, g_sums[rtprev * 32 + lane]);
    else hb = heads[lane];
    float q24 = qs[24 * 32 + lane];

    float lsum = 0.f;
    int nwarps = (gridDim.x * blockDim.x) >> 5;
    for (int n = (blockIdx.x * blockDim.x + tid) >> 5; n < N_; n += nwarps) {
        int p0 = g_rowptr[n], p1 = g_rowptr[n + 1];
        float acc;
        if (rtprev >= 0) {
            acc = memin[n * 32 + lane] * q24;
            for (int p = p0; p < p1; p++) {
                int pk = g_csrp[p];
                float wv = g_csrw[p];
                acc += qs[(pk & 31) * 32 + lane] * wv * memin[(pk >> 5) * 32 + lane];
            }
        } else {
            acc = (n == hb) ? q24 : 0.f;
            for (int p = p0; p < p1; p++) {
                int pk = g_csrp[p];
                float wv = g_csrw[p];
                float m = ((pk >> 5) == hb) ? 1.f : 0.f;
                acc += qs[(pk & 31) * 32 + lane] * wv * m;
            }
        }
        acc *= sp;
        memout[n * 32 + lane] = acc;
        lsum += acc;
    }
    red[wrp][lane] = lsum;
    __syncthreads();
    if (wrp == 0) {
        float s = 0.f;
#pragma unroll
        for (int q = 0; q < 8; q++) s += red[q][lane];
        atomicAdd(&g_sums[rt * 32 + lane], s);
    }
}

// ---------------- transposed accumulate into logits -----------------------------
__global__ void k_accum(const float* __restrict__ memlast, float* __restrict__ out, int rtl) {
    __shared__ float t[32][33];
    int n0 = blockIdx.x * 32;
    int tx = threadIdx.x & 31, ty = threadIdx.x >> 5;  // 256 thr: ty 0..7
#pragma unroll
    for (int j = 0; j < 32; j += 8) {
        int n = n0 + ty + j;
        if (n < N_) t[ty + j][tx] = memlast[n * 32 + tx];
    }
    __syncthreads();
    int n = n0 + tx;
    if (n < N_) {
#pragma unroll
        for (int j = 0; j < 32; j += 8) {
            int b = ty + j;
            float inv = 1.f / fmaxf(1e-20f, g_sums[rtl * 32 + b]);
            out[b * N_ + n] += t[tx][b] * inv;
        }
    }
}

// ---------------- host ----------------
extern "C" void kernel_launch(void* const* d_in, const int* in_sizes, int n_in,
                              void* d_out, int out_size) {
    const int* queries   = (const int*)d_in[0];
    const int* heads     = (const int*)d_in[1];
    const int* rels      = (const int*)d_in[2];
    const int* t_heads   = (const int*)d_in[3];
    const int* t_tails   = (const int*)d_in[4];
    const int* degrees   = (const int*)d_in[5];
    const float* q_emb   = (const float*)d_in[6];
    const float* ent_emb = (const float*)d_in[7];
    const float* q_Wih   = (const float*)d_in[8];
    const float* q_Whh   = (const float*)d_in[9];
    const float* q_bih   = (const float*)d_in[10];
    const float* q_bhh   = (const float*)d_in[11];
    const float* e_Wih   = (const float*)d_in[12];
    const float* e_Whh   = (const float*)d_in[13];
    const float* e_bih   = (const float*)d_in[14];
    const float* e_bhh   = (const float*)d_in[15];
    const float* q_lin_W = (const float*)d_in[16];
    const float* q_lin_b = (const float*)d_in[17];
    const float* e_lin_W = (const float*)d_in[18];
    const float* e_lin_b = (const float*)d_in[19];
    float* out = (float*)d_out;

    void *p_sums, *p_deg, *p_memA, *p_memB;
    cudaGetSymbolAddress(&p_sums, g_sums);
    cudaGetSymbolAddress(&p_deg, g_deg);
    cudaGetSymbolAddress(&p_memA, g_memA);
    cudaGetSymbolAddress(&p_memB, g_memB);
    float* memA = (float*)p_memA;
    float* memB = (float*)p_memB;

    cudaMemsetAsync(d_out, 0, (size_t)N_ * B_ * sizeof(float));
    cudaMemsetAsync(p_sums, 0, R_ * T_ * B_ * sizeof(float));
    cudaMemsetAsync(p_deg, 0, N_ * sizeof(int));

    k_xg<<<dim3(25, 2), 512>>>(ent_emb, e_Wih, e_bih, e_bhh);
    k_whhT<<<dim3(128, 2), 512>>>(e_Whh);
    k_deg<<<(E_ + 255) / 256, 256>>>(t_heads, t_tails);

    cudaFuncSetAttribute(k_entity2, cudaFuncAttributeMaxDynamicSharedMemorySize, ESMEM);
    k_entity2<<<dim3((N_ + 63) / 64, 2), 512, ESMEM>>>(degrees);

    k_scan<<<1, 1024>>>();
    k_eattn<<<782, 256>>>(e_lin_W, e_lin_b);
    k_w<<<(E_ + 255) / 256, 256>>>(rels, t_heads);
    k_fill<<<(E_ + 255) / 256, 256>>>(rels, t_heads, t_tails);

    k_qlstm<<<24, 256>>>(queries, q_emb, q_Wih, q_Whh, q_bih, q_bhh);
    k_qattn<<<36, 256>>>(q_lin_W, q_lin_b);

    for (int r = 0; r < R_; r++) {
        int rt0 = r * 3;
        k_prop<<<592, 256>>>(memA, memB, heads, rt0, -1);          // seed -> B
        k_prop<<<592, 256>>>(memB, memA, heads, rt0 + 1, rt0);     // B -> A
        k_prop<<<592, 256>>>(memA, memB, heads, rt0 + 2, rt0 + 1); // A -> B
        k_accum<<<(N_ + 31) / 32, 256>>>(memB, out, rt0 + 2);
    }
}

// round 7
// speedup vs baseline: 2.2445x; 1.0426x over previous
#include <cuda_runtime.h>
#include <math.h>

#define R_ 3
#define T_ 3
#define N_ 50000
#define OPS_ 24
#define E_ 400000
#define B_ 32
#define MAXDEG_ 8
#define QD_ 128
#define H_ 128

// ---------------- device scratch ----------------
__device__ float g_xgI[2 * 25 * 512];
__device__ float g_Wt[2 * 128 * 512];
__device__ float g_eh[N_ * 256];
__device__ float g_attn[N_ * OPS_];
__device__ float g_qys[R_ * 2 * T_ * B_ * H_];
__device__ float g_qaT[R_ * T_ * (OPS_ + 1) * B_];
__device__ float g_memA[N_ * B_];
__device__ float g_memB[N_ * B_];
__device__ float g_sums[R_ * T_ * B_];
__device__ int g_deg[N_];
__device__ int g_rowptr[N_ + 1];
__device__ int g_cursor[N_];
__device__ int2 g_csr2[2 * E_];   // {(src<<5)|relidx, w_bits}

__device__ __forceinline__ float sigm(float x) { return 1.f / (1.f + expf(-x)); }
__device__ __forceinline__ float tanh_fast(float x) {
    float y; asm("tanh.approx.f32 %0, %1;" : "=f"(y) : "f"(x)); return y;
}
__device__ __forceinline__ float sigm_fast(float x) { return 0.5f + 0.5f * tanh_fast(0.5f * x); }
__device__ __forceinline__ unsigned f2tf32(float x) {
    unsigned y; asm("cvt.rna.tf32.f32 %0, %1;" : "=r"(y) : "f"(x)); return y;
}
__device__ __forceinline__ void cpa16(float* dst, const float* src) {
    unsigned d = (unsigned)__cvta_generic_to_shared(dst);
    asm volatile("cp.async.ca.shared.global [%0], [%1], 16;" :: "r"(d), "l"(src));
}
__device__ __forceinline__ void mma8(float* c, unsigned a0, unsigned a1, unsigned a2,
                                     unsigned a3, unsigned b0, unsigned b1) {
    asm volatile("mma.sync.aligned.m16n8k8.row.col.f32.tf32.tf32.f32 "
                 "{%0,%1,%2,%3},{%4,%5,%6,%7},{%8,%9},{%0,%1,%2,%3};"
                 : "+f"(c[0]), "+f"(c[1]), "+f"(c[2]), "+f"(c[3])
                 : "r"(a0), "r"(a1), "r"(a2), "r"(a3), "r"(b0), "r"(b1));
}

// ---------------- precompute ----------------
__global__ void k_xg(const float* __restrict__ ent_emb, const float* __restrict__ e_Wih,
                     const float* __restrict__ e_bih, const float* __restrict__ e_bhh) {
    int d = blockIdx.x, dir = blockIdx.y, tid = threadIdx.x;
    int j = tid >> 2, g = tid & 3;
    int row = g * 128 + j;
    const float* w = e_Wih + (dir * 512 + row) * 128;
    const float* x = ent_emb + d * 128;
    float s = e_bih[dir * 512 + row] + e_bhh[dir * 512 + row];
    for (int k = 0; k < 128; k++) s += x[k] * w[k];
    g_xgI[(dir * 25 + d) * 512 + tid] = s;
}

__global__ void k_whhT(const float* __restrict__ e_Whh) {
    int k = blockIdx.x, dir = blockIdx.y, tid = threadIdx.x;
    int j = tid >> 2, g = tid & 3;
    float v = e_Whh[(dir * 512 + g * 128 + j) * 128 + k];
    g_Wt[(dir * 128 + k) * 512 + tid] = __uint_as_float(f2tf32(v));
}

// ---------------- CSR build ----------------
__global__ void k_deg(const int* __restrict__ t_heads, const int* __restrict__ t_tails) {
    int e = blockIdx.x * blockDim.x + threadIdx.x;
    if (e < E_) {
        atomicAdd(&g_deg[t_tails[e]], 1);
        atomicAdd(&g_deg[t_heads[e]], 1);
    }
}

__global__ void k_scan() {
    __shared__ int part[1024];
    int tid = threadIdx.x;
    int s = tid * 49, e = min(s + 49, N_);
    int sum = 0;
    for (int i = s; i < e; i++) sum += g_deg[i];
    part[tid] = sum;
    __syncthreads();
    for (int off = 1; off < 1024; off <<= 1) {
        int v = (tid >= off) ? part[tid - off] : 0;
        __syncthreads();
        part[tid] += v;
        __syncthreads();
    }
    int run = tid ? part[tid - 1] : 0;
    for (int i = s; i < e; i++) {
        g_rowptr[i] = run;
        g_cursor[i] = run;
        run += g_deg[i];
    }
    if (tid == 1023) g_rowptr[N_] = part[1023];
}

__global__ void k_fill(const int* __restrict__ rels, const int* __restrict__ t_heads,
                       const int* __restrict__ t_tails) {
    int e = blockIdx.x * blockDim.x + threadIdx.x;
    if (e >= E_) return;
    int rel = rels[e], hd = t_heads[e], tl = t_tails[e];
    int wb = __float_as_int(g_attn[hd * OPS_ + rel]);
    int p1 = atomicAdd(&g_cursor[tl], 1);
    g_csr2[p1] = make_int2((hd << 5) | rel, wb);
    int p2 = atomicAdd(&g_cursor[hd], 1);
    g_csr2[p2] = make_int2((tl << 5) | (rel + 12), wb);
}

// ---------------- entity BiLSTM (tf32 mma, permuted-k h layout) ----------------
// smem floats: hsm 64*136 | bsm 2*16*520 | xsm 25*516 | sdeg 512 ints
#define HSM 0
#define BSM 8704
#define XSM 25344
#define SDG 38244
#define ESMEM (38756 * 4)

__global__ void __launch_bounds__(512, 1) k_entity2(const int* __restrict__ degrees) {
    extern __shared__ float sm[];
    float* hsm = sm + HSM;
    float* bsm = sm + BSM;
    float* xsm = sm + XSM;
    int* sdeg = (int*)(sm + SDG);

    const int tid = threadIdx.x, lane = tid & 31, wid = tid >> 5;
    const int dir = blockIdx.y;
    const int n0 = blockIdx.x * 64;

    const float* xg = g_xgI + dir * 25 * 512;
    for (int i = tid; i < 25 * 512; i += 512)
        xsm[(i >> 9) * 516 + (i & 511)] = xg[i];
    {
        int row = tid >> 3, t = tid & 7, n = n0 + row;
        sdeg[tid] = (n < N_) ? degrees[n * 8 + (dir ? 7 - t : t)] : 0;
    }
    __syncthreads();

    const float* Wt = g_Wt + dir * 128 * 512;
    const int skr = tid >> 5, soff = (tid & 31) * 16;

    float cst[16];
#pragma unroll
    for (int i = 0; i < 16; i++) cst[i] = 0.f;

    for (int step = 0; step < 8; step++) {
        float acc[4][4][4];
#pragma unroll
        for (int mf = 0; mf < 4; mf++)
#pragma unroll
            for (int nf = 0; nf < 4; nf++)
#pragma unroll
                for (int q = 0; q < 4; q++) acc[mf][nf][q] = 0.f;

        if (step) {
            {   // stage chunk 0 -> buf 0
                float* d0 = bsm + skr * 520 + soff;
                const float* s0 = Wt + skr * 512 + soff;
#pragma unroll
                for (int q = 0; q < 4; q++) cpa16(d0 + q * 4, s0 + q * 4);
                asm volatile("cp.async.commit_group;");
            }
            for (int ch = 0; ch < 8; ch++) {
                asm volatile("cp.async.wait_group 0;");
                __syncthreads();   // staged data visible; prev buffer reads complete
                if (ch < 7) {
                    float* d0 = bsm + ((ch + 1) & 1) * 8320 + skr * 520 + soff;
                    const float* s0 = Wt + ((ch + 1) * 16 + skr) * 512 + soff;
#pragma unroll
                    for (int q = 0; q < 4; q++) cpa16(d0 + q * 4, s0 + q * 4);
                    asm volatile("cp.async.commit_group;");
                }
                const float* bf = bsm + (ch & 1) * 8320;
#pragma unroll
                for (int sub = 0; sub < 2; sub++) {
                    int kb = ch * 16 + sub * 8;
                    int kl = sub * 8 + (lane & 3);
                    unsigned b0[4], b1[4];
#pragma unroll
                    for (int nf = 0; nf < 4; nf++) {
                        int col = wid * 32 + nf * 8 + (lane >> 2);
                        b0[nf] = __float_as_uint(bf[kl * 520 + col]);
                        b1[nf] = __float_as_uint(bf[(kl + 4) * 520 + col]);
                    }
#pragma unroll
                    for (int mf = 0; mf < 4; mf++) {
                        int abase = (mf * 16 + (lane >> 2)) * 136 + kb + 2 * (lane & 3);
                        float2 v0 = *(const float2*)&hsm[abase];
                        float2 v1 = *(const float2*)&hsm[abase + 8 * 136];
#pragma unroll
                        for (int nf = 0; nf < 4; nf++)
                            mma8(acc[mf][nf], __float_as_uint(v0.x), __float_as_uint(v1.x),
                                 __float_as_uint(v0.y), __float_as_uint(v1.y), b0[nf], b1[nf]);
                    }
                }
            }
            __syncthreads();   // all MMA reads of hsm done before epilogue writes
        }

        int par = lane & 1;
#pragma unroll
        for (int mf = 0; mf < 4; mf++)
#pragma unroll
            for (int nf = 0; nf < 4; nf++) {
                float* a = acc[mf][nf];
                float x0 = __shfl_xor_sync(~0u, par ? a[0] : a[2], 1);
                float x1 = __shfl_xor_sync(~0u, par ? a[1] : a[3], 1);
                int row = mf * 16 + (lane >> 2) + 8 * par;
                int lo = nf * 2 + ((lane & 3) >> 1);
                int u = wid * 8 + lo;
                int d = sdeg[row * 8 + step];
                float4 xv = *(const float4*)&xsm[d * 516 + u * 4];
                float iv, fv, gv, ov;
                if (par) { iv = x0; fv = x1; gv = a[2]; ov = a[3]; }
                else     { iv = a[0]; fv = a[1]; gv = x0; ov = x1; }
                iv += xv.x; fv += xv.y; gv += xv.z; ov += xv.w;
                float c = cst[mf * 4 + nf];
                c = sigm_fast(fv) * c + sigm_fast(iv) * tanh_fast(gv);
                cst[mf * 4 + nf] = c;
                float h = sigm_fast(ov) * tanh_fast(c);
                if (step < 7) {
                    // permuted k storage: pairs (k, k+4) adjacent
                    int pos = wid * 8 + ((lo & 3) << 1) + (lo >> 2);
                    hsm[row * 136 + pos] = __uint_as_float(f2tf32(h));
                } else {
                    int n = n0 + row;
                    if (n < N_) g_eh[n * 256 + dir * 128 + u] = h;
                }
            }
        if (step == 0) __syncthreads();
    }
}

// ---------------- entity attention ----------------
__global__ void k_eattn(const float* __restrict__ e_lin_W, const float* __restrict__ e_lin_b) {
    __shared__ float sw[24 * 256];
    __shared__ float sb[24];
    int tid = threadIdx.x;
    for (int i = tid; i < 24 * 256; i += 256) sw[i] = e_lin_W[i];
    if (tid < 24) sb[tid] = e_lin_b[tid];
    __syncthreads();
    int lane = tid & 31;
    for (int n = blockIdx.x * 8 + (tid >> 5); n < N_; n += gridDim.x * 8) {
        float h[8];
        const float* hp = g_eh + n * 256;
#pragma unroll
        for (int j = 0; j < 8; j++) h[j] = hp[lane + 32 * j];
        float mine = -1e30f;
#pragma unroll
        for (int op = 0; op < 24; op++) {
            const float* wp = sw + op * 256 + lane;
            float s = 0.f;
#pragma unroll
            for (int j = 0; j < 8; j++) s += h[j] * wp[32 * j];
            for (int o = 16; o; o >>= 1) s += __shfl_xor_sync(~0u, s, o);
            if (lane == op) mine = s + sb[op];
        }
        float mx = mine;
        for (int o = 16; o; o >>= 1) mx = fmaxf(mx, __shfl_xor_sync(~0u, mx, o));
        float e = (lane < 24) ? expf(mine - mx) : 0.f;
        float sum = e;
        for (int o = 16; o; o >>= 1) sum += __shfl_xor_sync(~0u, sum, o);
        if (lane < 24) g_attn[n * 24 + lane] = e / sum;
    }
}

// ---------------- query path ----------------
__global__ void k_qlstm(const int* __restrict__ queries, const float* __restrict__ q_emb,
                        const float* __restrict__ q_Wih, const float* __restrict__ q_Whh,
                        const float* __restrict__ q_bih, const float* __restrict__ q_bhh) {
    int w = (blockIdx.x * blockDim.x + threadIdx.x) >> 5;
    int lane = threadIdx.x & 31;
    if (w >= R_ * 2 * B_) return;
    int b = w & 31, dir = (w >> 5) & 1, r = w >> 6;
    int rd = r * 2 + dir;
    const float* x = q_emb + queries[b] * QD_;
    const float* Wih = q_Wih + rd * 512 * 128;
    const float* Whh = q_Whh + rd * 512 * 128;
    float xw[4][4];
#pragma unroll
    for (int g = 0; g < 4; g++)
#pragma unroll
        for (int s = 0; s < 4; s++) {
            int row = g * 128 + lane + 32 * s;
            float acc = q_bih[rd * 512 + row] + q_bhh[rd * 512 + row];
            const float* wr = Wih + row * 128;
            for (int k = 0; k < 128; k++) acc += x[k] * wr[k];
            xw[g][s] = acc;
        }
    float h[4] = {0, 0, 0, 0}, c4[4] = {0, 0, 0, 0};
    for (int t = 0; t < T_; t++) {
        float gg[4][4];
#pragma unroll
        for (int g = 0; g < 4; g++)
#pragma unroll
            for (int s = 0; s < 4; s++) gg[g][s] = xw[g][s];
        for (int k = 0; k < 128; k++) {
            float hk = __shfl_sync(~0u, h[k >> 5], k & 31);
#pragma unroll
            for (int g = 0; g < 4; g++)
#pragma unroll
                for (int s = 0; s < 4; s++)
                    gg[g][s] += hk * Whh[(g * 128 + lane + 32 * s) * 128 + k];
        }
#pragma unroll
        for (int s = 0; s < 4; s++) {
            c4[s] = sigm(gg[1][s]) * c4[s] + sigm(gg[0][s]) * tanhf(gg[2][s]);
            h[s] = sigm(gg[3][s]) * tanhf(c4[s]);
        }
#pragma unroll
        for (int s = 0; s < 4; s++)
            g_qys[((rd * 3 + t) * B_ + b) * H_ + lane + 32 * s] = h[s];
    }
}

__global__ void k_qattn(const float* __restrict__ q_lin_W, const float* __restrict__ q_lin_b) {
    int w = (blockIdx.x * blockDim.x + threadIdx.x) >> 5;
    int lane = threadIdx.x & 31;
    if (w >= R_ * T_ * B_) return;
    int b = w & 31, t = (w >> 5) % 3, r = w / 96;
    const float* ysf = g_qys + (((r * 2 + 0) * 3 + t) * B_ + b) * H_;
    const float* ysb = g_qys + (((r * 2 + 1) * 3 + (2 - t)) * B_ + b) * H_;
    float s = -1e30f;
    if (lane <= OPS_) {
        s = q_lin_b[lane];
        const float* wv = q_lin_W + lane * 256;
        for (int k = 0; k < 128; k++) s += ysf[k] * wv[k];
        for (int k = 0; k < 128; k++) s += ysb[k] * wv[128 + k];
    }
    float mx = s;
    for (int o = 16; o; o >>= 1) mx = fmaxf(mx, __shfl_xor_sync(~0u, mx, o));
    float e = (lane <= OPS_) ? expf(s - mx) : 0.f;
    float sum = e;
    for (int o = 16; o; o >>= 1) sum += __shfl_xor_sync(~0u, sum, o);
    if (lane <= OPS_) g_qaT[((r * 3 + t) * (OPS_ + 1) + lane) * B_ + b] = e / sum;
}

// ---------------- fused propagation (batched CSR gather) ------------------------
__global__ void __launch_bounds__(256) k_prop(const float* __restrict__ memin,
                                              float* __restrict__ memout,
                                              const int* __restrict__ heads,
                                              int rt, int rtprev) {
    __shared__ float qs[25 * 32];
    __shared__ float red[8][32];
    int tid = threadIdx.x, lane = tid & 31, wrp = tid >> 5;
    const float* qsrc = g_qaT + rt * 25 * 32;
    for (int i = tid; i < 800; i += 256) qs[i] = qsrc[i];
    __syncthreads();

    float sp = 1.f;
    int hb = -1;
    if (rtprev >= 0) sp = 1.f / fmaxf(1e-20f, g_sums[rtprev * 32 + lane]);
    else hb = heads[lane];
    float q24 = qs[24 * 32 + lane];

    float lsum = 0.f;
    int nwarps = (gridDim.x * blockDim.x) >> 5;
    for (int n = (blockIdx.x * blockDim.x + tid) >> 5; n < N_; n += nwarps) {
        int p0 = g_rowptr[n], p1 = g_rowptr[n + 1];
        float acc;
        if (rtprev >= 0) {
            acc = memin[n * 32 + lane] * q24;
            int p = p0;
            for (; p + 4 <= p1; p += 4) {
                int2 e0 = g_csr2[p], e1 = g_csr2[p + 1], e2 = g_csr2[p + 2], e3 = g_csr2[p + 3];
                float m0 = memin[(e0.x >> 5) * 32 + lane];
                float m1 = memin[(e1.x >> 5) * 32 + lane];
                float m2 = memin[(e2.x >> 5) * 32 + lane];
                float m3 = memin[(e3.x >> 5) * 32 + lane];
                acc += qs[(e0.x & 31) * 32 + lane] * __int_as_float(e0.y) * m0;
                acc += qs[(e1.x & 31) * 32 + lane] * __int_as_float(e1.y) * m1;
                acc += qs[(e2.x & 31) * 32 + lane] * __int_as_float(e2.y) * m2;
                acc += qs[(e3.x & 31) * 32 + lane] * __int_as_float(e3.y) * m3;
            }
            for (; p < p1; p++) {
                int2 e = g_csr2[p];
                acc += qs[(e.x & 31) * 32 + lane] * __int_as_float(e.y) *
                       memin[(e.x >> 5) * 32 + lane];
            }
        } else {
            acc = (n == hb) ? q24 : 0.f;
            for (int p = p0; p < p1; p++) {
                int2 e = g_csr2[p];
                if ((e.x >> 5) == hb)
                    acc += qs[(e.x & 31) * 32 + lane] * __int_as_float(e.y);
            }
        }
        acc *= sp;
        memout[n * 32 + lane] = acc;
        lsum += acc;
    }
    red[wrp][lane] = lsum;
    __syncthreads();
    if (wrp == 0) {
        float s = 0.f;
#pragma unroll
        for (int q = 0; q < 8; q++) s += red[q][lane];
        atomicAdd(&g_sums[rt * 32 + lane], s);
    }
}

// ---------------- transposed accumulate into logits -----------------------------
__global__ void k_accum(const float* __restrict__ memlast, float* __restrict__ out, int rtl) {
    __shared__ float t[32][33];
    int n0 = blockIdx.x * 32;
    int tx = threadIdx.x & 31, ty = threadIdx.x >> 5;
#pragma unroll
    for (int j = 0; j < 32; j += 8) {
        int n = n0 + ty + j;
        if (n < N_) t[ty + j][tx] = memlast[n * 32 + tx];
    }
    __syncthreads();
    int n = n0 + tx;
    if (n < N_) {
#pragma unroll
        for (int j = 0; j < 32; j += 8) {
            int b = ty + j;
            float inv = 1.f / fmaxf(1e-20f, g_sums[rtl * 32 + b]);
            out[b * N_ + n] += t[tx][b] * inv;
        }
    }
}

// ---------------- host ----------------
extern "C" void kernel_launch(void* const* d_in, const int* in_sizes, int n_in,
                              void* d_out, int out_size) {
    const int* queries   = (const int*)d_in[0];
    const int* heads     = (const int*)d_in[1];
    const int* rels      = (const int*)d_in[2];
    const int* t_heads   = (const int*)d_in[3];
    const int* t_tails   = (const int*)d_in[4];
    const int* degrees   = (const int*)d_in[5];
    const float* q_emb   = (const float*)d_in[6];
    const float* ent_emb = (const float*)d_in[7];
    const float* q_Wih   = (const float*)d_in[8];
    const float* q_Whh   = (const float*)d_in[9];
    const float* q_bih   = (const float*)d_in[10];
    const float* q_bhh   = (const float*)d_in[11];
    const float* e_Wih   = (const float*)d_in[12];
    const float* e_Whh   = (const float*)d_in[13];
    const float* e_bih   = (const float*)d_in[14];
    const float* e_bhh   = (const float*)d_in[15];
    const float* q_lin_W = (const float*)d_in[16];
    const float* q_lin_b = (const float*)d_in[17];
    const float* e_lin_W = (const float*)d_in[18];
    const float* e_lin_b = (const float*)d_in[19];
    float* out = (float*)d_out;

    void *p_sums, *p_deg, *p_memA, *p_memB;
    cudaGetSymbolAddress(&p_sums, g_sums);
    cudaGetSymbolAddress(&p_deg, g_deg);
    cudaGetSymbolAddress(&p_memA, g_memA);
    cudaGetSymbolAddress(&p_memB, g_memB);
    float* memA = (float*)p_memA;
    float* memB = (float*)p_memB;

    cudaMemsetAsync(d_out, 0, (size_t)N_ * B_ * sizeof(float));
    cudaMemsetAsync(p_sums, 0, R_ * T_ * B_ * sizeof(float));
    cudaMemsetAsync(p_deg, 0, N_ * sizeof(int));

    k_xg<<<dim3(25, 2), 512>>>(ent_emb, e_Wih, e_bih, e_bhh);
    k_whhT<<<dim3(128, 2), 512>>>(e_Whh);
    k_deg<<<(E_ + 255) / 256, 256>>>(t_heads, t_tails);

    cudaFuncSetAttribute(k_entity2, cudaFuncAttributeMaxDynamicSharedMemorySize, ESMEM);
    k_entity2<<<dim3((N_ + 63) / 64, 2), 512, ESMEM>>>(degrees);

    k_scan<<<1, 1024>>>();
    k_eattn<<<782, 256>>>(e_lin_W, e_lin_b);
    k_fill<<<(E_ + 255) / 256, 256>>>(rels, t_heads, t_tails);

    k_qlstm<<<24, 256>>>(queries, q_emb, q_Wih, q_Whh, q_bih, q_bhh);
    k_qattn<<<36, 256>>>(q_lin_W, q_lin_b);

    for (int r = 0; r < R_; r++) {
        int rt0 = r * 3;
        k_prop<<<592, 256>>>(memA, memB, heads, rt0, -1);
        k_prop<<<592, 256>>>(memB, memA, heads, rt0 + 1, rt0);
        k_prop<<<592, 256>>>(memA, memB, heads, rt0 + 2, rt0 + 1);
        k_accum<<<(N_ + 31) / 32, 256>>>(memB, out, rt0 + 2);
    }
}

// round 8
// speedup vs baseline: 2.3223x; 1.0347x over previous
#include <cuda_runtime.h>
#include <math.h>

#define R_ 3
#define T_ 3
#define N_ 50000
#define OPS_ 24
#define E_ 400000
#define B_ 32
#define MAXDEG_ 8
#define QD_ 128
#define H_ 128

// ---------------- device scratch ----------------
__device__ float g_xgI[2 * 25 * 512];
__device__ float g_Wt[2 * 128 * 512];
__device__ float g_hcls[2 * 625 * 128];   // class h after 2 steps (tf32, hsm-permuted)
__device__ float g_ccls[2 * 625 * 128];   // class c after 2 steps (plain, by unit)
__device__ float g_eh[N_ * 256];
__device__ float g_attn[N_ * OPS_];
__device__ float g_qys[R_ * 2 * T_ * B_ * H_];
__device__ float g_qaT[R_ * T_ * (OPS_ + 1) * B_];
__device__ float g_memA[N_ * B_];
__device__ float g_memB[N_ * B_];
__device__ float g_sums[R_ * T_ * B_];
__device__ int g_deg[N_];
__device__ int g_rowptr[N_ + 1];
__device__ int g_cursor[N_];
__device__ int2 g_csr2[2 * E_];   // {(src<<5)|relidx, w_bits}

__device__ __forceinline__ float sigm(float x) { return 1.f / (1.f + expf(-x)); }
__device__ __forceinline__ float tanh_fast(float x) {
    float y; asm("tanh.approx.f32 %0, %1;" : "=f"(y) : "f"(x)); return y;
}
__device__ __forceinline__ float sigm_fast(float x) { return 0.5f + 0.5f * tanh_fast(0.5f * x); }
__device__ __forceinline__ unsigned f2tf32(float x) {
    unsigned y; asm("cvt.rna.tf32.f32 %0, %1;" : "=r"(y) : "f"(x)); return y;
}
__device__ __forceinline__ void cpa16(float* dst, const float* src) {
    unsigned d = (unsigned)__cvta_generic_to_shared(dst);
    asm volatile("cp.async.ca.shared.global [%0], [%1], 16;" :: "r"(d), "l"(src));
}
__device__ __forceinline__ void mma8(float* c, unsigned a0, unsigned a1, unsigned a2,
                                     unsigned a3, unsigned b0, unsigned b1) {
    asm volatile("mma.sync.aligned.m16n8k8.row.col.f32.tf32.tf32.f32 "
                 "{%0,%1,%2,%3},{%4,%5,%6,%7},{%8,%9},{%0,%1,%2,%3};"
                 : "+f"(c[0]), "+f"(c[1]), "+f"(c[2]), "+f"(c[3])
                 : "r"(a0), "r"(a1), "r"(a2), "r"(a3), "r"(b0), "r"(b1));
}

// ---------------- precompute ----------------
__global__ void k_xg(const float* __restrict__ ent_emb, const float* __restrict__ e_Wih,
                     const float* __restrict__ e_bih, const float* __restrict__ e_bhh) {
    int d = blockIdx.x, dir = blockIdx.y, tid = threadIdx.x;
    int j = tid >> 2, g = tid & 3;
    int row = g * 128 + j;
    const float* w = e_Wih + (dir * 512 + row) * 128;
    const float* x = ent_emb + d * 128;
    float s = e_bih[dir * 512 + row] + e_bhh[dir * 512 + row];
    for (int k = 0; k < 128; k++) s += x[k] * w[k];
    g_xgI[(dir * 25 + d) * 512 + tid] = s;
}

__global__ void k_whhT(const float* __restrict__ e_Whh) {
    int k = blockIdx.x, dir = blockIdx.y, tid = threadIdx.x;
    int j = tid >> 2, g = tid & 3;
    float v = e_Whh[(dir * 512 + g * 128 + j) * 128 + k];
    g_Wt[(dir * 128 + k) * 512 + tid] = __uint_as_float(f2tf32(v));
}

// ---------------- class table: LSTM steps 0..1 for all 625 (d0,d1) prefixes -----
__global__ void k_cls() {
    __shared__ float sh0[8][128];
    int warp = threadIdx.x >> 5, lane = threadIdx.x & 31;
    int cls = blockIdx.x * 8 + warp;
    int dir = blockIdx.y;
    if (cls >= 625) return;
    int d0 = cls / 25, d1 = cls - d0 * 25;
    const float* xg0 = g_xgI + (dir * 25 + d0) * 512;
    const float* xg1 = g_xgI + (dir * 25 + d1) * 512;
    const float* Wt = g_Wt + dir * 128 * 512;

    float c0[4], h0[4];
#pragma unroll
    for (int q = 0; q < 4; q++) {
        int u = lane + 32 * q;
        float4 xv = *(const float4*)&xg0[u * 4];
        c0[q] = sigm_fast(xv.x) * tanh_fast(xv.z);
        h0[q] = sigm_fast(xv.w) * tanh_fast(c0[q]);
        sh0[warp][u] = __uint_as_float(f2tf32(h0[q]));
    }
    __syncwarp();

#pragma unroll
    for (int q = 0; q < 4; q++) {
        int u = lane + 32 * q;
        float4 acc = *(const float4*)&xg1[u * 4];
        for (int k = 0; k < 128; k++) {
            float hk = sh0[warp][k];
            float4 w4 = *(const float4*)&Wt[k * 512 + u * 4];
            acc.x += hk * w4.x; acc.y += hk * w4.y;
            acc.z += hk * w4.z; acc.w += hk * w4.w;
        }
        float c1 = sigm_fast(acc.y) * c0[q] + sigm_fast(acc.x) * tanh_fast(acc.z);
        float h1 = sigm_fast(acc.w) * tanh_fast(c1);
        // store h permuted to hsm layout: within each 8-unit group, pos = ((lo&3)<<1)|(lo>>2)
        int lo = u & 7;
        int pos = (u & ~7) + ((lo & 3) << 1) + (lo >> 2);
        g_hcls[(dir * 625 + cls) * 128 + pos] = __uint_as_float(f2tf32(h1));
        g_ccls[(dir * 625 + cls) * 128 + u] = c1;
    }
}

// ---------------- CSR build ----------------
__global__ void k_deg(const int* __restrict__ t_heads, const int* __restrict__ t_tails) {
    int e = blockIdx.x * blockDim.x + threadIdx.x;
    if (e < E_) {
        atomicAdd(&g_deg[t_tails[e]], 1);
        atomicAdd(&g_deg[t_heads[e]], 1);
    }
}

__global__ void k_scan() {
    __shared__ int part[1024];
    int tid = threadIdx.x;
    int s = tid * 49, e = min(s + 49, N_);
    int sum = 0;
    for (int i = s; i < e; i++) sum += g_deg[i];
    part[tid] = sum;
    __syncthreads();
    for (int off = 1; off < 1024; off <<= 1) {
        int v = (tid >= off) ? part[tid - off] : 0;
        __syncthreads();
        part[tid] += v;
        __syncthreads();
    }
    int run = tid ? part[tid - 1] : 0;
    for (int i = s; i < e; i++) {
        g_rowptr[i] = run;
        g_cursor[i] = run;
        run += g_deg[i];
    }
    if (tid == 1023) g_rowptr[N_] = part[1023];
}

__global__ void k_fill(const int* __restrict__ rels, const int* __restrict__ t_heads,
                       const int* __restrict__ t_tails) {
    int e = blockIdx.x * blockDim.x + threadIdx.x;
    if (e >= E_) return;
    int rel = rels[e], hd = t_heads[e], tl = t_tails[e];
    int wb = __float_as_int(g_attn[hd * OPS_ + rel]);
    int p1 = atomicAdd(&g_cursor[tl], 1);
    g_csr2[p1] = make_int2((hd << 5) | rel, wb);
    int p2 = atomicAdd(&g_cursor[hd], 1);
    g_csr2[p2] = make_int2((tl << 5) | (rel + 12), wb);
}

// ---------------- entity BiLSTM steps 2..7 (tf32 mma, class-table init) ---------
// smem floats: hsm 64*136 | bsm 2*16*520 | xsm 25*516 | sdeg 512 int | scls 64 int
#define HSM 0
#define BSM 8704
#define XSM 25344
#define SDG 38244
#define SCL 38756
#define ESMEM (38820 * 4)

__global__ void __launch_bounds__(512, 1) k_entity2(const int* __restrict__ degrees) {
    extern __shared__ float sm[];
    float* hsm = sm + HSM;
    float* bsm = sm + BSM;
    float* xsm = sm + XSM;
    int* sdeg = (int*)(sm + SDG);
    int* scls = (int*)(sm + SCL);

    const int tid = threadIdx.x, lane = tid & 31, wid = tid >> 5;
    const int dir = blockIdx.y;
    const int n0 = blockIdx.x * 64;

    const float* xg = g_xgI + dir * 25 * 512;
    for (int i = tid; i < 25 * 512; i += 512)
        xsm[(i >> 9) * 516 + (i & 511)] = xg[i];
    {
        int row = tid >> 3, t = tid & 7, n = n0 + row;
        sdeg[tid] = (n < N_) ? degrees[n * 8 + (dir ? 7 - t : t)] : 0;
    }
    __syncthreads();
    if (tid < 64) scls[tid] = sdeg[tid * 8] * 25 + sdeg[tid * 8 + 1];
    __syncthreads();

    // init h from class table (already tf32 + permuted)
    for (int i = tid; i < 64 * 128; i += 512) {
        int row = i >> 7, col = i & 127;
        hsm[row * 136 + col] = g_hcls[(dir * 625 + scls[row]) * 128 + col];
    }

    const float* Wt = g_Wt + dir * 128 * 512;
    const int skr = tid >> 5, soff = (tid & 31) * 16;
    const int par = lane & 1;

    // init c from class table
    float cst[16];
#pragma unroll
    for (int mf = 0; mf < 4; mf++)
#pragma unroll
        for (int nf = 0; nf < 4; nf++) {
            int row = mf * 16 + (lane >> 2) + 8 * par;
            int u = wid * 8 + nf * 2 + ((lane & 3) >> 1);
            cst[mf * 4 + nf] = g_ccls[(dir * 625 + scls[row]) * 128 + u];
        }
    __syncthreads();

    for (int step = 2; step < 8; step++) {
        float acc[4][4][4];
#pragma unroll
        for (int mf = 0; mf < 4; mf++)
#pragma unroll
            for (int nf = 0; nf < 4; nf++)
#pragma unroll
                for (int q = 0; q < 4; q++) acc[mf][nf][q] = 0.f;

        {   // stage chunk 0 -> buf 0
            float* d0 = bsm + skr * 520 + soff;
            const float* s0 = Wt + skr * 512 + soff;
#pragma unroll
            for (int q = 0; q < 4; q++) cpa16(d0 + q * 4, s0 + q * 4);
            asm volatile("cp.async.commit_group;");
        }
        for (int ch = 0; ch < 8; ch++) {
            asm volatile("cp.async.wait_group 0;");
            __syncthreads();
            if (ch < 7) {
                float* d0 = bsm + ((ch + 1) & 1) * 8320 + skr * 520 + soff;
                const float* s0 = Wt + ((ch + 1) * 16 + skr) * 512 + soff;
#pragma unroll
                for (int q = 0; q < 4; q++) cpa16(d0 + q * 4, s0 + q * 4);
                asm volatile("cp.async.commit_group;");
            }
            const float* bf = bsm + (ch & 1) * 8320;
#pragma unroll
            for (int sub = 0; sub < 2; sub++) {
                int kb = ch * 16 + sub * 8;
                int kl = sub * 8 + (lane & 3);
                unsigned b0[4], b1[4];
#pragma unroll
                for (int nf = 0; nf < 4; nf++) {
                    int col = wid * 32 + nf * 8 + (lane >> 2);
                    b0[nf] = __float_as_uint(bf[kl * 520 + col]);
                    b1[nf] = __float_as_uint(bf[(kl + 4) * 520 + col]);
                }
#pragma unroll
                for (int mf = 0; mf < 4; mf++) {
                    int abase = (mf * 16 + (lane >> 2)) * 136 + kb + 2 * (lane & 3);
                    float2 v0 = *(const float2*)&hsm[abase];
                    float2 v1 = *(const float2*)&hsm[abase + 8 * 136];
#pragma unroll
                    for (int nf = 0; nf < 4; nf++)
                        mma8(acc[mf][nf], __float_as_uint(v0.x), __float_as_uint(v1.x),
                             __float_as_uint(v0.y), __float_as_uint(v1.y), b0[nf], b1[nf]);
                }
            }
        }
        __syncthreads();   // MMA reads of hsm done before epilogue writes

#pragma unroll
        for (int mf = 0; mf < 4; mf++)
#pragma unroll
            for (int nf = 0; nf < 4; nf++) {
                float* a = acc[mf][nf];
                float x0 = __shfl_xor_sync(~0u, par ? a[0] : a[2], 1);
                float x1 = __shfl_xor_sync(~0u, par ? a[1] : a[3], 1);
                int row = mf * 16 + (lane >> 2) + 8 * par;
                int lo = nf * 2 + ((lane & 3) >> 1);
                int u = wid * 8 + lo;
                int d = sdeg[row * 8 + step];
                float4 xv = *(const float4*)&xsm[d * 516 + u * 4];
                float iv, fv, gv, ov;
                if (par) { iv = x0; fv = x1; gv = a[2]; ov = a[3]; }
                else     { iv = a[0]; fv = a[1]; gv = x0; ov = x1; }
                iv += xv.x; fv += xv.y; gv += xv.z; ov += xv.w;
                float c = cst[mf * 4 + nf];
                c = sigm_fast(fv) * c + sigm_fast(iv) * tanh_fast(gv);
                cst[mf * 4 + nf] = c;
                float h = sigm_fast(ov) * tanh_fast(c);
                if (step < 7) {
                    int pos = wid * 8 + ((lo & 3) << 1) + (lo >> 2);
                    hsm[row * 136 + pos] = __uint_as_float(f2tf32(h));
                } else {
                    int n = n0 + row;
                    if (n < N_) g_eh[n * 256 + dir * 128 + u] = h;
                }
            }
    }
}

// ---------------- entity attention ----------------
__global__ void k_eattn(const float* __restrict__ e_lin_W, const float* __restrict__ e_lin_b) {
    __shared__ float sw[24 * 256];
    __shared__ float sb[24];
    int tid = threadIdx.x;
    for (int i = tid; i < 24 * 256; i += 256) sw[i] = e_lin_W[i];
    if (tid < 24) sb[tid] = e_lin_b[tid];
    __syncthreads();
    int lane = tid & 31;
    for (int n = blockIdx.x * 8 + (tid >> 5); n < N_; n += gridDim.x * 8) {
        float h[8];
        const float* hp = g_eh + n * 256;
#pragma unroll
        for (int j = 0; j < 8; j++) h[j] = hp[lane + 32 * j];
        float mine = -1e30f;
#pragma unroll
        for (int op = 0; op < 24; op++) {
            const float* wp = sw + op * 256 + lane;
            float s = 0.f;
#pragma unroll
            for (int j = 0; j < 8; j++) s += h[j] * wp[32 * j];
            for (int o = 16; o; o >>= 1) s += __shfl_xor_sync(~0u, s, o);
            if (lane == op) mine = s + sb[op];
        }
        float mx = mine;
        for (int o = 16; o; o >>= 1) mx = fmaxf(mx, __shfl_xor_sync(~0u, mx, o));
        float e = (lane < 24) ? expf(mine - mx) : 0.f;
        float sum = e;
        for (int o = 16; o; o >>= 1) sum += __shfl_xor_sync(~0u, sum, o);
        if (lane < 24) g_attn[n * 24 + lane] = e / sum;
    }
}

// ---------------- query path ----------------
__global__ void k_qlstm(const int* __restrict__ queries, const float* __restrict__ q_emb,
                        const float* __restrict__ q_Wih, const float* __restrict__ q_Whh,
                        const float* __restrict__ q_bih, const float* __restrict__ q_bhh) {
    int w = (blockIdx.x * blockDim.x + threadIdx.x) >> 5;
    int lane = threadIdx.x & 31;
    if (w >= R_ * 2 * B_) return;
    int b = w & 31, dir = (w >> 5) & 1, r = w >> 6;
    int rd = r * 2 + dir;
    const float* x = q_emb + queries[b] * QD_;
    const float* Wih = q_Wih + rd * 512 * 128;
    const float* Whh = q_Whh + rd * 512 * 128;
    float xw[4][4];
#pragma unroll
    for (int g = 0; g < 4; g++)
#pragma unroll
        for (int s = 0; s < 4; s++) {
            int row = g * 128 + lane + 32 * s;
            float acc = q_bih[rd * 512 + row] + q_bhh[rd * 512 + row];
            const float* wr = Wih + row * 128;
            for (int k = 0; k < 128; k++) acc += x[k] * wr[k];
            xw[g][s] = acc;
        }
    float h[4] = {0, 0, 0, 0}, c4[4] = {0, 0, 0, 0};
    for (int t = 0; t < T_; t++) {
        float gg[4][4];
#pragma unroll
        for (int g = 0; g < 4; g++)
#pragma unroll
            for (int s = 0; s < 4; s++) gg[g][s] = xw[g][s];
        for (int k = 0; k < 128; k++) {
            float hk = __shfl_sync(~0u, h[k >> 5], k & 31);
#pragma unroll
            for (int g = 0; g < 4; g++)
#pragma unroll
                for (int s = 0; s < 4; s++)
                    gg[g][s] += hk * Whh[(g * 128 + lane + 32 * s) * 128 + k];
        }
#pragma unroll
        for (int s = 0; s < 4; s++) {
            c4[s] = sigm(gg[1][s]) * c4[s] + sigm(gg[0][s]) * tanhf(gg[2][s]);
            h[s] = sigm(gg[3][s]) * tanhf(c4[s]);
        }
#pragma unroll
        for (int s = 0; s < 4; s++)
            g_qys[((rd * 3 + t) * B_ + b) * H_ + lane + 32 * s] = h[s];
    }
}

__global__ void k_qattn(const float* __restrict__ q_lin_W, const float* __restrict__ q_lin_b) {
    int w = (blockIdx.x * blockDim.x + threadIdx.x) >> 5;
    int lane = threadIdx.x & 31;
    if (w >= R_ * T_ * B_) return;
    int b = w & 31, t = (w >> 5) % 3, r = w / 96;
    const float* ysf = g_qys + (((r * 2 + 0) * 3 + t) * B_ + b) * H_;
    const float* ysb = g_qys + (((r * 2 + 1) * 3 + (2 - t)) * B_ + b) * H_;
    float s = -1e30f;
    if (lane <= OPS_) {
        s = q_lin_b[lane];
        const float* wv = q_lin_W + lane * 256;
        for (int k = 0; k < 128; k++) s += ysf[k] * wv[k];
        for (int k = 0; k < 128; k++) s += ysb[k] * wv[128 + k];
    }
    float mx = s;
    for (int o = 16; o; o >>= 1) mx = fmaxf(mx, __shfl_xor_sync(~0u, mx, o));
    float e = (lane <= OPS_) ? expf(s - mx) : 0.f;
    float sum = e;
    for (int o = 16; o; o >>= 1) sum += __shfl_xor_sync(~0u, sum, o);
    if (lane <= OPS_) g_qaT[((r * 3 + t) * (OPS_ + 1) + lane) * B_ + b] = e / sum;
}

// ---------------- fused propagation (batched CSR gather) ------------------------
__global__ void __launch_bounds__(256) k_prop(const float* __restrict__ memin,
                                              float* __restrict__ memout,
                                              const int* __restrict__ heads,
                                              int rt, int rtprev) {
    __shared__ float qs[25 * 32];
    __shared__ float red[8][32];
    int tid = threadIdx.x, lane = tid & 31, wrp = tid >> 5;
    const float* qsrc = g_qaT + rt * 25 * 32;
    for (int i = tid; i < 800; i += 256) qs[i] = qsrc[i];
    __syncthreads();

    float sp = 1.f;
    int hb = -1;
    if (rtprev >= 0) sp = 1.f / fmaxf(1e-20f, g_sums[rtprev * 32 + lane]);
    else hb = heads[lane];
    float q24 = qs[24 * 32 + lane];

    float lsum = 0.f;
    int nwarps = (gridDim.x * blockDim.x) >> 5;
    for (int n = (blockIdx.x * blockDim.x + tid) >> 5; n < N_; n += nwarps) {
        int p0 = g_rowptr[n], p1 = g_rowptr[n + 1];
        float acc;
        if (rtprev >= 0) {
            acc = memin[n * 32 + lane] * q24;
            int p = p0;
            for (; p + 8 <= p1; p += 8) {
                int2 ee[8];
                float mm[8];
#pragma unroll
                for (int j = 0; j < 8; j++) ee[j] = g_csr2[p + j];
#pragma unroll
                for (int j = 0; j < 8; j++) mm[j] = memin[(ee[j].x >> 5) * 32 + lane];
#pragma unroll
                for (int j = 0; j < 8; j++)
                    acc += qs[(ee[j].x & 31) * 32 + lane] * __int_as_float(ee[j].y) * mm[j];
            }
            for (; p < p1; p++) {
                int2 e = g_csr2[p];
                acc += qs[(e.x & 31) * 32 + lane] * __int_as_float(e.y) *
                       memin[(e.x >> 5) * 32 + lane];
            }
        } else {
            acc = (n == hb) ? q24 : 0.f;
            for (int p = p0; p < p1; p++) {
                int2 e = g_csr2[p];
                if ((e.x >> 5) == hb)
                    acc += qs[(e.x & 31) * 32 + lane] * __int_as_float(e.y);
            }
        }
        acc *= sp;
        memout[n * 32 + lane] = acc;
        lsum += acc;
    }
    red[wrp][lane] = lsum;
    __syncthreads();
    if (wrp == 0) {
        float s = 0.f;
#pragma unroll
        for (int q = 0; q < 8; q++) s += red[q][lane];
        atomicAdd(&g_sums[rt * 32 + lane], s);
    }
}

// ---------------- transposed accumulate into logits -----------------------------
__global__ void k_accum(const float* __restrict__ memlast, float* __restrict__ out, int rtl) {
    __shared__ float t[32][33];
    int n0 = blockIdx.x * 32;
    int tx = threadIdx.x & 31, ty = threadIdx.x >> 5;
#pragma unroll
    for (int j = 0; j < 32; j += 8) {
        int n = n0 + ty + j;
        if (n < N_) t[ty + j][tx] = memlast[n * 32 + tx];
    }
    __syncthreads();
    int n = n0 + tx;
    if (n < N_) {
#pragma unroll
        for (int j = 0; j < 32; j += 8) {
            int b = ty + j;
            float inv = 1.f / fmaxf(1e-20f, g_sums[rtl * 32 + b]);
            out[b * N_ + n] += t[tx][b] * inv;
        }
    }
}

// ---------------- host ----------------
extern "C" void kernel_launch(void* const* d_in, const int* in_sizes, int n_in,
                              void* d_out, int out_size) {
    const int* queries   = (const int*)d_in[0];
    const int* heads     = (const int*)d_in[1];
    const int* rels      = (const int*)d_in[2];
    const int* t_heads   = (const int*)d_in[3];
    const int* t_tails   = (const int*)d_in[4];
    const int* degrees   = (const int*)d_in[5];
    const float* q_emb   = (const float*)d_in[6];
    const float* ent_emb = (const float*)d_in[7];
    const float* q_Wih   = (const float*)d_in[8];
    const float* q_Whh   = (const float*)d_in[9];
    const float* q_bih   = (const float*)d_in[10];
    const float* q_bhh   = (const float*)d_in[11];
    const float* e_Wih   = (const float*)d_in[12];
    const float* e_Whh   = (const float*)d_in[13];
    const float* e_bih   = (const float*)d_in[14];
    const float* e_bhh   = (const float*)d_in[15];
    const float* q_lin_W = (const float*)d_in[16];
    const float* q_lin_b = (const float*)d_in[17];
    const float* e_lin_W = (const float*)d_in[18];
    const float* e_lin_b = (const float*)d_in[19];
    float* out = (float*)d_out;

    void *p_sums, *p_deg, *p_memA, *p_memB;
    cudaGetSymbolAddress(&p_sums, g_sums);
    cudaGetSymbolAddress(&p_deg, g_deg);
    cudaGetSymbolAddress(&p_memA, g_memA);
    cudaGetSymbolAddress(&p_memB, g_memB);
    float* memA = (float*)p_memA;
    float* memB = (float*)p_memB;

    cudaMemsetAsync(d_out, 0, (size_t)N_ * B_ * sizeof(float));
    cudaMemsetAsync(p_sums, 0, R_ * T_ * B_ * sizeof(float));
    cudaMemsetAsync(p_deg, 0, N_ * sizeof(int));

    k_xg<<<dim3(25, 2), 512>>>(ent_emb, e_Wih, e_bih, e_bhh);
    k_whhT<<<dim3(128, 2), 512>>>(e_Whh);
    k_cls<<<dim3(79, 2), 256>>>();
    k_deg<<<(E_ + 255) / 256, 256>>>(t_heads, t_tails);

    cudaFuncSetAttribute(k_entity2, cudaFuncAttributeMaxDynamicSharedMemorySize, ESMEM);
    k_entity2<<<dim3((N_ + 63) / 64, 2), 512, ESMEM>>>(degrees);

    k_scan<<<1, 1024>>>();
    k_eattn<<<782, 256>>>(e_lin_W, e_lin_b);
    k_fill<<<(E_ + 255) / 256, 256>>>(rels, t_heads, t_tails);

    k_qlstm<<<24, 256>>>(queries, q_emb, q_Wih, q_Whh, q_bih, q_bhh);
    k_qattn<<<36, 256>>>(q_lin_W, q_lin_b);

    for (int r = 0; r < R_; r++) {
        int rt0 = r * 3;
        k_prop<<<592, 256>>>(memA, memB, heads, rt0, -1);
        k_prop<<<592, 256>>>(memB, memA, heads, rt0 + 1, rt0);
        k_prop<<<592, 256>>>(memA, memB, heads, rt0 + 2, rt0 + 1);
        k_accum<<<(N_ + 31) / 32, 256>>>(memB, out, rt0 + 2);
    }
}